// round 1
// baseline (speedup 1.0000x reference)
#include <cuda_runtime.h>
#include <math.h>

#define BATCH 2
#define SEQ 2048
#define DIM 2048
#define HEADS 16
#define HD 128
#define DI 2048           /* HEADS*HD */
#define MTOT (BATCH*SEQ)  /* 4096 */

// ---------------- scratch (device globals: allocation-free rule) ------------
__device__ float g_q[(size_t)MTOT * DI];
__device__ float g_k[(size_t)MTOT * DI];
__device__ float g_v[(size_t)MTOT * DI];
__device__ float g_o[(size_t)MTOT * DI];
__device__ float g_rinv[4][DIM];   // 0:Wq rows, 1:Wk rows, 2:Wv rows, 3:Wout cols

// ---------------- weight row-norm reciprocal (l2 over last dim) -------------
__global__ void rownorm_kernel(const float* __restrict__ W, int sel) {
    __shared__ float red[8];
    const int row = blockIdx.x;
    const int tid = threadIdx.x;
    const float4* p4 = (const float4*)(W + (size_t)row * DIM);
    float s = 0.f;
    #pragma unroll
    for (int i = tid; i < DIM / 4; i += 256) {
        float4 v = p4[i];
        s += v.x * v.x + v.y * v.y + v.z * v.z + v.w * v.w;
    }
    #pragma unroll
    for (int off = 16; off; off >>= 1) s += __shfl_xor_sync(0xffffffffu, s, off);
    if ((tid & 31) == 0) red[tid >> 5] = s;
    __syncthreads();
    if (tid == 0) {
        float t = 0.f;
        #pragma unroll
        for (int i = 0; i < 8; i++) t += red[i];
        g_rinv[sel][row] = 1.f / fmaxf(sqrtf(t), 1e-12f);
    }
}

// ---------------- Wout column-norm reciprocal (l2 over dim 0) ---------------
__global__ void colnorm_kernel(const float* __restrict__ W) {
    const int col = blockIdx.x * 256 + threadIdx.x;
    float s = 0.f;
    for (int r = 0; r < DIM; ++r) {
        float v = W[(size_t)r * DI + col];
        s += v * v;
    }
    g_rinv[3][col] = 1.f / fmaxf(sqrtf(s), 1e-12f);
}

// ---------------- NT SGEMM: C[m,n] = sum_k A[m,k]*B[n,k]  (*rinv[n]) --------
// 128x128x16 tile, 256 threads, 8x8 microtile, double-buffered smem.
__global__ void __launch_bounds__(256) gemm_nt_kernel(
    const float* __restrict__ A, const float* __restrict__ B,
    float* __restrict__ C, const float* __restrict__ rinv,
    int M, int N, int K)
{
    __shared__ float As[2][16][128];
    __shared__ float Bs[2][16][128];
    const int tid = threadIdx.x;
    const int bx = blockIdx.x, by = blockIdx.y;
    const int lr = tid >> 2;              // 0..63
    const int lc = (tid & 3) << 2;        // 0,4,8,12
    const float* Ap = A + (size_t)(by * 128 + lr) * K + lc;
    const float* Bp = B + (size_t)(bx * 128 + lr) * K + lc;
    const size_t s64 = (size_t)64 * K;
    const int ty = tid >> 4, tx = tid & 15;

    float acc[8][8];
    #pragma unroll
    for (int i = 0; i < 8; i++)
        #pragma unroll
        for (int j = 0; j < 8; j++) acc[i][j] = 0.f;

    // prologue: tile 0 -> buf 0
    {
        float4 a0 = *(const float4*)Ap;
        float4 a1 = *(const float4*)(Ap + s64);
        float4 b0 = *(const float4*)Bp;
        float4 b1 = *(const float4*)(Bp + s64);
        As[0][lc + 0][lr] = a0.x; As[0][lc + 1][lr] = a0.y;
        As[0][lc + 2][lr] = a0.z; As[0][lc + 3][lr] = a0.w;
        As[0][lc + 0][lr + 64] = a1.x; As[0][lc + 1][lr + 64] = a1.y;
        As[0][lc + 2][lr + 64] = a1.z; As[0][lc + 3][lr + 64] = a1.w;
        Bs[0][lc + 0][lr] = b0.x; Bs[0][lc + 1][lr] = b0.y;
        Bs[0][lc + 2][lr] = b0.z; Bs[0][lc + 3][lr] = b0.w;
        Bs[0][lc + 0][lr + 64] = b1.x; Bs[0][lc + 1][lr + 64] = b1.y;
        Bs[0][lc + 2][lr + 64] = b1.z; Bs[0][lc + 3][lr + 64] = b1.w;
    }
    __syncthreads();

    const int nkt = K >> 4;
    int buf = 0;
    for (int kt = 0; kt < nkt; ++kt) {
        float4 na0, na1, nb0, nb1;
        const bool hn = (kt + 1) < nkt;
        if (hn) {
            const float* Ap2 = Ap + (kt + 1) * 16;
            const float* Bp2 = Bp + (kt + 1) * 16;
            na0 = *(const float4*)Ap2;
            na1 = *(const float4*)(Ap2 + s64);
            nb0 = *(const float4*)Bp2;
            nb1 = *(const float4*)(Bp2 + s64);
        }
        #pragma unroll
        for (int kk = 0; kk < 16; kk++) {
            float4 x0 = *(const float4*)&As[buf][kk][ty * 8];
            float4 x1 = *(const float4*)&As[buf][kk][ty * 8 + 4];
            float4 y0 = *(const float4*)&Bs[buf][kk][tx * 8];
            float4 y1 = *(const float4*)&Bs[buf][kk][tx * 8 + 4];
            float av[8] = {x0.x, x0.y, x0.z, x0.w, x1.x, x1.y, x1.z, x1.w};
            float bv[8] = {y0.x, y0.y, y0.z, y0.w, y1.x, y1.y, y1.z, y1.w};
            #pragma unroll
            for (int i = 0; i < 8; i++)
                #pragma unroll
                for (int j = 0; j < 8; j++)
                    acc[i][j] = fmaf(av[i], bv[j], acc[i][j]);
        }
        if (hn) {
            const int nb = buf ^ 1;
            As[nb][lc + 0][lr] = na0.x; As[nb][lc + 1][lr] = na0.y;
            As[nb][lc + 2][lr] = na0.z; As[nb][lc + 3][lr] = na0.w;
            As[nb][lc + 0][lr + 64] = na1.x; As[nb][lc + 1][lr + 64] = na1.y;
            As[nb][lc + 2][lr + 64] = na1.z; As[nb][lc + 3][lr + 64] = na1.w;
            Bs[nb][lc + 0][lr] = nb0.x; Bs[nb][lc + 1][lr] = nb0.y;
            Bs[nb][lc + 2][lr] = nb0.z; Bs[nb][lc + 3][lr] = nb0.w;
            Bs[nb][lc + 0][lr + 64] = nb1.x; Bs[nb][lc + 1][lr + 64] = nb1.y;
            Bs[nb][lc + 2][lr + 64] = nb1.z; Bs[nb][lc + 3][lr + 64] = nb1.w;
            __syncthreads();
            buf = nb;
        }
    }

    float sc[8];
    #pragma unroll
    for (int j = 0; j < 8; j++)
        sc[j] = rinv ? rinv[bx * 128 + tx * 8 + j] : 1.f;
    #pragma unroll
    for (int i = 0; i < 8; i++) {
        float* cp = C + (size_t)(by * 128 + ty * 8 + i) * N + bx * 128 + tx * 8;
        float4 o0 = make_float4(acc[i][0] * sc[0], acc[i][1] * sc[1],
                                acc[i][2] * sc[2], acc[i][3] * sc[3]);
        float4 o1 = make_float4(acc[i][4] * sc[4], acc[i][5] * sc[5],
                                acc[i][6] * sc[6], acc[i][7] * sc[7]);
        *(float4*)cp = o0;
        *(float4*)(cp + 4) = o1;
    }
}

// ---------------- per-head l2norm of q,k + fold qk_scale*DIM*sqrt(HD) into q
__global__ void headnorm_kernel(const float* __restrict__ qk_scale) {
    const int w = blockIdx.x * 8 + (threadIdx.x >> 5);
    const int lane = threadIdx.x & 31;
    const int tensor = w >> 16;              // 0:q 1:k
    const int v = w & 65535;                 // (b*SEQ+n)*HEADS + h
    const int h = v & 15;
    float* base = (tensor ? g_k : g_q) + (size_t)(v >> 4) * DI + (size_t)h * HD;
    float4 x = *(const float4*)(base + lane * 4);
    float ss = x.x * x.x + x.y * x.y + x.z * x.z + x.w * x.w;
    #pragma unroll
    for (int off = 16; off; off >>= 1) ss += __shfl_xor_sync(0xffffffffu, ss, off);
    const float rinv = 1.f / fmaxf(sqrtf(ss), 1e-12f);
    if (tensor == 0) {
        const float mul = 2048.0f * 11.313708498984761f;   // DIM * sqrt(HD)
        float4 s4 = *(const float4*)(qk_scale + (size_t)h * HD + lane * 4);
        x.x *= rinv * s4.x * mul;
        x.y *= rinv * s4.y * mul;
        x.z *= rinv * s4.z * mul;
        x.w *= rinv * s4.w * mul;
    } else {
        x.x *= rinv; x.y *= rinv; x.z *= rinv; x.w *= rinv;
    }
    *(float4*)(base + lane * 4) = x;
}

// ---------------- causal flash attention (fp32), 64x64 tiles, D=128 ---------
// out[b,n,e] = (softmax row)/l * rinv_wout[e] written to g_o
#define QK_STRIDE 132
#define PS_STRIDE 66

__global__ void __launch_bounds__(256) attn_kernel() {
    extern __shared__ float sm[];
    float* Qs = sm;                         // [64][132]
    float* Ks = Qs + 64 * QK_STRIDE;        // [64][132]
    float* Vs = Ks + 64 * QK_STRIDE;        // [64][132]
    float* Ps = Vs + 64 * QK_STRIDE;        // [64][66]

    const int tid = threadIdx.x;
    const int qt = 31 - blockIdx.x;         // longest work first
    const int bh = blockIdx.y;
    const int b = bh >> 4, h = bh & 15;
    const size_t base = (size_t)b * SEQ * DI + (size_t)h * HD;
    const float* qg = g_q + base;
    const float* kg = g_k + base;
    const float* vg = g_v + base;
    float* og = g_o + base;

    // load Q tile
    #pragma unroll
    for (int it = 0; it < 8; ++it) {
        int idx = tid + it * 256;
        int r = idx >> 5;
        int c = (idx & 31) << 2;
        *(float4*)(Qs + r * QK_STRIDE + c) =
            *(const float4*)(qg + (size_t)(qt * 64 + r) * DI + c);
    }

    const int ty = tid >> 4, tx = tid & 15;
    float m_i[4] = {-1e30f, -1e30f, -1e30f, -1e30f};
    float l_i[4] = {0.f, 0.f, 0.f, 0.f};
    float acc[4][8];
    #pragma unroll
    for (int i = 0; i < 4; i++)
        #pragma unroll
        for (int c = 0; c < 8; c++) acc[i][c] = 0.f;

    for (int kt = 0; kt <= qt; ++kt) {
        __syncthreads();   // prev PV done (and Q load on first iter)
        #pragma unroll
        for (int it = 0; it < 8; ++it) {
            int idx = tid + it * 256;
            int r = idx >> 5;
            int c = (idx & 31) << 2;
            size_t go = (size_t)(kt * 64 + r) * DI + c;
            *(float4*)(Ks + r * QK_STRIDE + c) = *(const float4*)(kg + go);
            *(float4*)(Vs + r * QK_STRIDE + c) = *(const float4*)(vg + go);
        }
        __syncthreads();

        // S = Q K^T (scales pre-folded into q)
        float s[4][4];
        #pragma unroll
        for (int i = 0; i < 4; i++)
            #pragma unroll
            for (int j = 0; j < 4; j++) s[i][j] = 0.f;
        #pragma unroll 2
        for (int d = 0; d < HD; d += 4) {
            float4 av[4], bv[4];
            #pragma unroll
            for (int i = 0; i < 4; i++)
                av[i] = *(const float4*)(Qs + (ty * 4 + i) * QK_STRIDE + d);
            #pragma unroll
            for (int j = 0; j < 4; j++)
                bv[j] = *(const float4*)(Ks + (tx * 4 + j) * QK_STRIDE + d);
            #pragma unroll
            for (int i = 0; i < 4; i++)
                #pragma unroll
                for (int j = 0; j < 4; j++)
                    s[i][j] += av[i].x * bv[j].x + av[i].y * bv[j].y +
                               av[i].z * bv[j].z + av[i].w * bv[j].w;
        }
        if (kt == qt) {
            #pragma unroll
            for (int i = 0; i < 4; i++)
                #pragma unroll
                for (int j = 0; j < 4; j++)
                    if (tx * 4 + j > ty * 4 + i) s[i][j] = -1e30f;
        }

        // online softmax (row stats across 16 lanes of a half-warp)
        #pragma unroll
        for (int i = 0; i < 4; i++) {
            float mm = fmaxf(fmaxf(s[i][0], s[i][1]), fmaxf(s[i][2], s[i][3]));
            mm = fmaxf(mm, __shfl_xor_sync(0xffffffffu, mm, 1));
            mm = fmaxf(mm, __shfl_xor_sync(0xffffffffu, mm, 2));
            mm = fmaxf(mm, __shfl_xor_sync(0xffffffffu, mm, 4));
            mm = fmaxf(mm, __shfl_xor_sync(0xffffffffu, mm, 8));
            float mnew = fmaxf(m_i[i], mm);
            float scl = __expf(m_i[i] - mnew);
            m_i[i] = mnew;
            float rs = 0.f;
            #pragma unroll
            for (int j = 0; j < 4; j++) {
                float p = __expf(s[i][j] - mnew);
                Ps[(ty * 4 + i) * PS_STRIDE + tx * 4 + j] = p;
                rs += p;
            }
            rs += __shfl_xor_sync(0xffffffffu, rs, 1);
            rs += __shfl_xor_sync(0xffffffffu, rs, 2);
            rs += __shfl_xor_sync(0xffffffffu, rs, 4);
            rs += __shfl_xor_sync(0xffffffffu, rs, 8);
            l_i[i] = l_i[i] * scl + rs;
            #pragma unroll
            for (int c = 0; c < 8; c++) acc[i][c] *= scl;
        }
        __syncthreads();   // Ps visible

        // O += P V
        #pragma unroll 2
        for (int j = 0; j < 64; ++j) {
            float4 v0 = *(const float4*)(Vs + j * QK_STRIDE + tx * 8);
            float4 v1 = *(const float4*)(Vs + j * QK_STRIDE + tx * 8 + 4);
            #pragma unroll
            for (int i = 0; i < 4; i++) {
                float p = Ps[(ty * 4 + i) * PS_STRIDE + j];
                acc[i][0] = fmaf(p, v0.x, acc[i][0]);
                acc[i][1] = fmaf(p, v0.y, acc[i][1]);
                acc[i][2] = fmaf(p, v0.z, acc[i][2]);
                acc[i][3] = fmaf(p, v0.w, acc[i][3]);
                acc[i][4] = fmaf(p, v1.x, acc[i][4]);
                acc[i][5] = fmaf(p, v1.y, acc[i][5]);
                acc[i][6] = fmaf(p, v1.z, acc[i][6]);
                acc[i][7] = fmaf(p, v1.w, acc[i][7]);
            }
        }
    }

    // epilogue: /l, fold Wout column-norm reciprocal
    float ro[8];
    {
        const float* rp = &g_rinv[3][h * HD + tx * 8];
        float4 r0 = *(const float4*)rp;
        float4 r1 = *(const float4*)(rp + 4);
        ro[0] = r0.x; ro[1] = r0.y; ro[2] = r0.z; ro[3] = r0.w;
        ro[4] = r1.x; ro[5] = r1.y; ro[6] = r1.z; ro[7] = r1.w;
    }
    #pragma unroll
    for (int i = 0; i < 4; i++) {
        float inv = 1.f / l_i[i];
        float* op = og + (size_t)(qt * 64 + ty * 4 + i) * DI + tx * 8;
        float4 o0 = make_float4(acc[i][0] * inv * ro[0], acc[i][1] * inv * ro[1],
                                acc[i][2] * inv * ro[2], acc[i][3] * inv * ro[3]);
        float4 o1 = make_float4(acc[i][4] * inv * ro[4], acc[i][5] * inv * ro[5],
                                acc[i][6] * inv * ro[6], acc[i][7] * inv * ro[7]);
        *(float4*)op = o0;
        *(float4*)(op + 4) = o1;
    }
}

// ---------------------------------------------------------------------------
extern "C" void kernel_launch(void* const* d_in, const int* in_sizes, int n_in,
                              void* d_out, int out_size) {
    (void)in_sizes; (void)n_in; (void)out_size;
    const float* x    = (const float*)d_in[0];
    const float* Wq   = (const float*)d_in[1];
    const float* Wk   = (const float*)d_in[2];
    const float* Wv   = (const float*)d_in[3];
    const float* Wout = (const float*)d_in[4];
    const float* qk   = (const float*)d_in[5];
    float* out = (float*)d_out;

    float *pq, *pk, *pv, *po, *pr;
    cudaGetSymbolAddress((void**)&pq, g_q);
    cudaGetSymbolAddress((void**)&pk, g_k);
    cudaGetSymbolAddress((void**)&pv, g_v);
    cudaGetSymbolAddress((void**)&po, g_o);
    cudaGetSymbolAddress((void**)&pr, g_rinv);

    rownorm_kernel<<<DIM, 256>>>(Wq, 0);
    rownorm_kernel<<<DIM, 256>>>(Wk, 1);
    rownorm_kernel<<<DIM, 256>>>(Wv, 2);
    colnorm_kernel<<<DIM / 256, 256>>>(Wout);

    dim3 gg(DI / 128, MTOT / 128);   // (16, 32)
    gemm_nt_kernel<<<gg, 256>>>(x, Wq, pq, pr + 0 * DIM, MTOT, DI, DIM);
    gemm_nt_kernel<<<gg, 256>>>(x, Wk, pk, pr + 1 * DIM, MTOT, DI, DIM);
    gemm_nt_kernel<<<gg, 256>>>(x, Wv, pv, pr + 2 * DIM, MTOT, DI, DIM);

    headnorm_kernel<<<(2 * MTOT * HEADS) / 8, 256>>>(qk);

    const size_t asmem = (size_t)(3 * 64 * QK_STRIDE + 64 * PS_STRIDE) * sizeof(float);
    cudaFuncSetAttribute(attn_kernel, cudaFuncAttributeMaxDynamicSharedMemorySize,
                         (int)asmem);
    attn_kernel<<<dim3(SEQ / 64, BATCH * HEADS), 256, asmem>>>();

    gemm_nt_kernel<<<gg, 256>>>(po, Wout, out, nullptr, MTOT, DIM, DI);
}

// round 3
// speedup vs baseline: 1.3489x; 1.3489x over previous
#include <cuda_runtime.h>
#include <cuda_bf16.h>
#include <math.h>
#include <stdint.h>

#define BATCH 2
#define SEQ 2048
#define DIM 2048
#define HEADS 16
#define HD 128
#define DI 2048           /* HEADS*HD */
#define MTOT (BATCH*SEQ)  /* 4096 */

// ---------------- scratch (device globals: allocation-free rule) ------------
__device__ float g_q[(size_t)MTOT * DI];
__device__ float g_k[(size_t)MTOT * DI];
__device__ float g_v[(size_t)MTOT * DI];
__device__ float g_rinv[4][DIM];   // 0:Wq rows, 1:Wk rows, 2:Wv rows, 3:Wout cols

__device__ __nv_bfloat16 g_xh[(size_t)MTOT * DIM];
__device__ __nv_bfloat16 g_xl[(size_t)MTOT * DIM];
__device__ __nv_bfloat16 g_wh[4][(size_t)DIM * DIM];  // q,k,v,out
__device__ __nv_bfloat16 g_wl[4][(size_t)DIM * DIM];
__device__ __nv_bfloat16 g_oh[(size_t)MTOT * DI];
__device__ __nv_bfloat16 g_ol[(size_t)MTOT * DI];

// ============================ PTX helpers (sm_80+ portable) =================
__device__ __forceinline__ uint32_t smem_u32(const void* p) {
    uint32_t a;
    asm("{ .reg .u64 t; cvta.to.shared.u64 t, %1; cvt.u32.u64 %0, t; }"
        : "=r"(a) : "l"(p));
    return a;
}

__device__ __forceinline__ void cp16(uint32_t saddr, const void* g) {
    asm volatile("cp.async.cg.shared.global [%0], [%1], 16;"
                 :: "r"(saddr), "l"(g) : "memory");
}
#define CP_COMMIT() asm volatile("cp.async.commit_group;" ::: "memory")
#define CP_WAIT(n)  asm volatile("cp.async.wait_group %0;" :: "n"(n) : "memory")

#define LDSM_X4(r, addr) \
    asm volatile("ldmatrix.sync.aligned.m8n8.x4.shared.b16 {%0,%1,%2,%3}, [%4];" \
        : "=r"((r)[0]), "=r"((r)[1]), "=r"((r)[2]), "=r"((r)[3]) : "r"(addr))

#define MMA16816(d, a, b0, b1) \
    asm volatile("mma.sync.aligned.m16n8k16.row.col.f32.bf16.bf16.f32 " \
        "{%0,%1,%2,%3}, {%4,%5,%6,%7}, {%8,%9}, {%0,%1,%2,%3};" \
        : "+f"((d)[0]), "+f"((d)[1]), "+f"((d)[2]), "+f"((d)[3]) \
        : "r"((a)[0]), "r"((a)[1]), "r"((a)[2]), "r"((a)[3]), "r"(b0), "r"(b1))

// ================= fp32 -> bf16 hi/lo converters (+ fused norms) ============
__global__ void convert_x_kernel(const float4* __restrict__ x,
                                 __nv_bfloat162* __restrict__ hi,
                                 __nv_bfloat162* __restrict__ lo) {
    int i = blockIdx.x * 256 + threadIdx.x;
    float4 v = x[i];
    __nv_bfloat16 h0 = __float2bfloat16(v.x), h1 = __float2bfloat16(v.y);
    __nv_bfloat16 h2 = __float2bfloat16(v.z), h3 = __float2bfloat16(v.w);
    hi[2 * i] = __nv_bfloat162(h0, h1);
    hi[2 * i + 1] = __nv_bfloat162(h2, h3);
    lo[2 * i] = __nv_bfloat162(__float2bfloat16(v.x - __bfloat162float(h0)),
                               __float2bfloat16(v.y - __bfloat162float(h1)));
    lo[2 * i + 1] = __nv_bfloat162(__float2bfloat16(v.z - __bfloat162float(h2)),
                                   __float2bfloat16(v.w - __bfloat162float(h3)));
}

// one block per weight row: convert + row l2 norm reciprocal
__global__ void convert_w_kernel(const float* __restrict__ W,
                                 __nv_bfloat16* __restrict__ hi,
                                 __nv_bfloat16* __restrict__ lo, int sel) {
    __shared__ float red[8];
    const int row = blockIdx.x, tid = threadIdx.x;
    const float4* p = (const float4*)(W + (size_t)row * DIM);
    __nv_bfloat162* hp = (__nv_bfloat162*)(hi + (size_t)row * DIM);
    __nv_bfloat162* lp = (__nv_bfloat162*)(lo + (size_t)row * DIM);
    float s = 0.f;
    #pragma unroll
    for (int i = tid; i < DIM / 4; i += 256) {
        float4 v = p[i];
        s += v.x * v.x + v.y * v.y + v.z * v.z + v.w * v.w;
        __nv_bfloat16 h0 = __float2bfloat16(v.x), h1 = __float2bfloat16(v.y);
        __nv_bfloat16 h2 = __float2bfloat16(v.z), h3 = __float2bfloat16(v.w);
        hp[2 * i] = __nv_bfloat162(h0, h1);
        hp[2 * i + 1] = __nv_bfloat162(h2, h3);
        lp[2 * i] = __nv_bfloat162(__float2bfloat16(v.x - __bfloat162float(h0)),
                                   __float2bfloat16(v.y - __bfloat162float(h1)));
        lp[2 * i + 1] = __nv_bfloat162(__float2bfloat16(v.z - __bfloat162float(h2)),
                                       __float2bfloat16(v.w - __bfloat162float(h3)));
    }
    #pragma unroll
    for (int off = 16; off; off >>= 1) s += __shfl_xor_sync(0xffffffffu, s, off);
    if ((tid & 31) == 0) red[tid >> 5] = s;
    __syncthreads();
    if (tid == 0) {
        float t = 0.f;
        #pragma unroll
        for (int i = 0; i < 8; i++) t += red[i];
        g_rinv[sel][row] = 1.f / fmaxf(sqrtf(t), 1e-12f);
    }
}

// Wout elementwise convert (no norm fused; col-norm is separate, deterministic)
__global__ void convert_wout_kernel(const float4* __restrict__ W,
                                    __nv_bfloat162* __restrict__ hi,
                                    __nv_bfloat162* __restrict__ lo) {
    int i = blockIdx.x * 256 + threadIdx.x;
    float4 v = W[i];
    __nv_bfloat16 h0 = __float2bfloat16(v.x), h1 = __float2bfloat16(v.y);
    __nv_bfloat16 h2 = __float2bfloat16(v.z), h3 = __float2bfloat16(v.w);
    hi[2 * i] = __nv_bfloat162(h0, h1);
    hi[2 * i + 1] = __nv_bfloat162(h2, h3);
    lo[2 * i] = __nv_bfloat162(__float2bfloat16(v.x - __bfloat162float(h0)),
                               __float2bfloat16(v.y - __bfloat162float(h1)));
    lo[2 * i + 1] = __nv_bfloat162(__float2bfloat16(v.z - __bfloat162float(h2)),
                                   __float2bfloat16(v.w - __bfloat162float(h3)));
}

// Wout column-norm reciprocal (l2 over dim 0), deterministic serial reduce
__global__ void colnorm_kernel(const float* __restrict__ W) {
    const int col = blockIdx.x * 256 + threadIdx.x;
    float s = 0.f;
    for (int r = 0; r < DIM; ++r) {
        float v = W[(size_t)r * DI + col];
        s += v * v;
    }
    g_rinv[3][col] = 1.f / fmaxf(sqrtf(s), 1e-12f);
}

// =================== HMMA split-bf16 NT GEMM ================================
// C[m,n] = sum_k A[m,k]*B[n,k] (*rinv[n]); A,B bf16 hi/lo, K stride = 2048.
// 128x128x32 CTA tile, 256 thr (8 warps 4x2), warp tile 32x64, double buffer.
// smem layout per stage: Ah | Al | Bh | Bl, each 8KB, stored as pre-arranged
// 16B ldmatrix rows: every ldmatrix.x4 reads 512 contiguous bytes.
#define GBM 128
#define GBK 32
#define G_NKT (DIM / GBK)       /* 64 */
#define G_MAT 8192
#define G_STAGE 32768

__global__ void __launch_bounds__(256) hmma_gemm_kernel(
    const __nv_bfloat16* __restrict__ Ahg, const __nv_bfloat16* __restrict__ Alg,
    const __nv_bfloat16* __restrict__ Bhg, const __nv_bfloat16* __restrict__ Blg,
    float* __restrict__ C, const float* __restrict__ rinv, int ldc)
{
    extern __shared__ char smem[];
    const uint32_t sb = smem_u32(smem);
    const int tid = threadIdx.x;
    const int wid = tid >> 5, lane = tid & 31;
    const int wm = wid & 3, wn = wid >> 2;
    const int mbase = blockIdx.y * GBM;
    const int nbase = blockIdx.x * GBM;

    // ---- stage loader: 2 chunks/thread/matrix, placed in ldmatrix order ----
    auto load_stage = [&](int kt, int buf) {
        const uint32_t st = sb + buf * G_STAGE;
        const int koff = kt * GBK;
        #pragma unroll
        for (int half = 0; half < 2; ++half) {
            const int cid = tid + half * 256;
            const int r = cid >> 2, c = cid & 3;
            // A tile order: (m0-7,kh0)(m8-15,kh0)(m0-7,kh1)(m8-15,kh1)
            const uint32_t aoff = ((c >> 1) << 12) + ((r >> 4) << 9) +
                (((r & 7) + ((r >> 3) & 1) * 8 + (c & 1) * 16) << 4);
            // B tile order: (n0-7,kh0)(n0-7,kh1)(n8-15,kh0)(n8-15,kh1)
            const uint32_t boff = ((c >> 1) << 12) + ((r >> 4) << 9) +
                (((r & 7) + (c & 1) * 8 + ((r >> 3) & 1) * 16) << 4);
            const size_t ga = (size_t)(mbase + r) * DIM + koff + c * 8;
            const size_t gb = (size_t)(nbase + r) * DIM + koff + c * 8;
            cp16(st + aoff, Ahg + ga);
            cp16(st + G_MAT + aoff, Alg + ga);
            cp16(st + 2 * G_MAT + boff, Bhg + gb);
            cp16(st + 3 * G_MAT + boff, Blg + gb);
        }
    };

    float acc[2][8][4];
    #pragma unroll
    for (int i = 0; i < 2; i++)
        #pragma unroll
        for (int j = 0; j < 8; j++)
            #pragma unroll
            for (int t = 0; t < 4; t++) acc[i][j][t] = 0.f;

    load_stage(0, 0); CP_COMMIT();
    load_stage(1, 1); CP_COMMIT();
    CP_WAIT(1);
    __syncthreads();

    for (int kt = 0; kt < G_NKT; ++kt) {
        const int buf = kt & 1;
        const uint32_t stg = sb + buf * G_STAGE;
        #pragma unroll
        for (int s = 0; s < 2; ++s) {   // two k16 slabs per ktile
            const uint32_t aAddr = stg + (s << 12) + ((wm * 2) << 9) + lane * 16;
            const uint32_t bAddr = stg + 2 * G_MAT + (s << 12) + ((wn * 4) << 9) + lane * 16;
            uint32_t ah0[4], ah1[4], al0[4], al1[4], b[4][4];
            LDSM_X4(ah0, aAddr);
            LDSM_X4(ah1, aAddr + 512);
            LDSM_X4(al0, aAddr + G_MAT);
            LDSM_X4(al1, aAddr + G_MAT + 512);
            #pragma unroll
            for (int jt = 0; jt < 4; ++jt) LDSM_X4(b[jt], bAddr + jt * 512);
            // pass1: Ah*Bh ; pass3: Al*Bh
            #pragma unroll
            for (int jt = 0; jt < 4; ++jt) {
                MMA16816(acc[0][2 * jt],     ah0, b[jt][0], b[jt][1]);
                MMA16816(acc[0][2 * jt + 1], ah0, b[jt][2], b[jt][3]);
                MMA16816(acc[1][2 * jt],     ah1, b[jt][0], b[jt][1]);
                MMA16816(acc[1][2 * jt + 1], ah1, b[jt][2], b[jt][3]);
                MMA16816(acc[0][2 * jt],     al0, b[jt][0], b[jt][1]);
                MMA16816(acc[0][2 * jt + 1], al0, b[jt][2], b[jt][3]);
                MMA16816(acc[1][2 * jt],     al1, b[jt][0], b[jt][1]);
                MMA16816(acc[1][2 * jt + 1], al1, b[jt][2], b[jt][3]);
            }
            // pass2: Ah*Bl (reuse b regs)
            #pragma unroll
            for (int jt = 0; jt < 4; ++jt) LDSM_X4(b[jt], bAddr + G_MAT + jt * 512);
            #pragma unroll
            for (int jt = 0; jt < 4; ++jt) {
                MMA16816(acc[0][2 * jt],     ah0, b[jt][0], b[jt][1]);
                MMA16816(acc[0][2 * jt + 1], ah0, b[jt][2], b[jt][3]);
                MMA16816(acc[1][2 * jt],     ah1, b[jt][0], b[jt][1]);
                MMA16816(acc[1][2 * jt + 1], ah1, b[jt][2], b[jt][3]);
            }
        }
        __syncthreads();
        if (kt + 2 < G_NKT) {
            load_stage(kt + 2, buf);
            CP_COMMIT();
            CP_WAIT(1);
        } else {
            CP_WAIT(0);
        }
        __syncthreads();
    }

    // ---- epilogue: scale by rinv[n], store fp32 ----
    const int r0 = mbase + wm * 32 + (lane >> 2);
    #pragma unroll
    for (int j = 0; j < 8; ++j) {
        const int col = nbase + wn * 64 + j * 8 + (lane & 3) * 2;
        const float s0 = rinv ? rinv[col] : 1.f;
        const float s1 = rinv ? rinv[col + 1] : 1.f;
        #pragma unroll
        for (int i = 0; i < 2; ++i) {
            const int row = r0 + i * 16;
            float2 d0 = make_float2(acc[i][j][0] * s0, acc[i][j][1] * s1);
            float2 d1 = make_float2(acc[i][j][2] * s0, acc[i][j][3] * s1);
            *(float2*)(C + (size_t)row * ldc + col) = d0;
            *(float2*)(C + (size_t)(row + 8) * ldc + col) = d1;
        }
    }
}

// ---------------- per-head l2norm of q,k + fold qk_scale*DIM*sqrt(HD) into q
__global__ void headnorm_kernel(const float* __restrict__ qk_scale) {
    const int w = blockIdx.x * 8 + (threadIdx.x >> 5);
    const int lane = threadIdx.x & 31;
    const int tensor = w >> 16;              // 0:q 1:k
    const int v = w & 65535;                 // (b*SEQ+n)*HEADS + h
    const int h = v & 15;
    float* base = (tensor ? g_k : g_q) + (size_t)(v >> 4) * DI + (size_t)h * HD;
    float4 x = *(const float4*)(base + lane * 4);
    float ss = x.x * x.x + x.y * x.y + x.z * x.z + x.w * x.w;
    #pragma unroll
    for (int off = 16; off; off >>= 1) ss += __shfl_xor_sync(0xffffffffu, ss, off);
    const float rinv = 1.f / fmaxf(sqrtf(ss), 1e-12f);
    if (tensor == 0) {
        const float mul = 2048.0f * 11.313708498984761f;   // DIM * sqrt(HD)
        float4 s4 = *(const float4*)(qk_scale + (size_t)h * HD + lane * 4);
        x.x *= rinv * s4.x * mul;
        x.y *= rinv * s4.y * mul;
        x.z *= rinv * s4.z * mul;
        x.w *= rinv * s4.w * mul;
    } else {
        x.x *= rinv; x.y *= rinv; x.z *= rinv; x.w *= rinv;
    }
    *(float4*)(base + lane * 4) = x;
}

// ---------------- causal flash attention (fp32), 64x64 tiles, D=128 ---------
#define QK_STRIDE 132
#define PS_STRIDE 66

__global__ void __launch_bounds__(256) attn_kernel() {
    extern __shared__ float sm[];
    float* Qs = sm;                         // [64][132]
    float* Ks = Qs + 64 * QK_STRIDE;        // [64][132]
    float* Vs = Ks + 64 * QK_STRIDE;        // [64][132]
    float* Ps = Vs + 64 * QK_STRIDE;        // [64][66]

    const int tid = threadIdx.x;
    const int qt = 31 - blockIdx.x;         // longest work first
    const int bh = blockIdx.y;
    const int b = bh >> 4, h = bh & 15;
    const size_t base = (size_t)b * SEQ * DI + (size_t)h * HD;
    const float* qg = g_q + base;
    const float* kg = g_k + base;
    const float* vg = g_v + base;
    __nv_bfloat16* ohp = g_oh + base;
    __nv_bfloat16* olp = g_ol + base;

    #pragma unroll
    for (int it = 0; it < 8; ++it) {
        int idx = tid + it * 256;
        int r = idx >> 5;
        int c = (idx & 31) << 2;
        *(float4*)(Qs + r * QK_STRIDE + c) =
            *(const float4*)(qg + (size_t)(qt * 64 + r) * DI + c);
    }

    const int ty = tid >> 4, tx = tid & 15;
    float m_i[4] = {-1e30f, -1e30f, -1e30f, -1e30f};
    float l_i[4] = {0.f, 0.f, 0.f, 0.f};
    float acc[4][8];
    #pragma unroll
    for (int i = 0; i < 4; i++)
        #pragma unroll
        for (int c = 0; c < 8; c++) acc[i][c] = 0.f;

    for (int kt = 0; kt <= qt; ++kt) {
        __syncthreads();
        #pragma unroll
        for (int it = 0; it < 8; ++it) {
            int idx = tid + it * 256;
            int r = idx >> 5;
            int c = (idx & 31) << 2;
            size_t go = (size_t)(kt * 64 + r) * DI + c;
            *(float4*)(Ks + r * QK_STRIDE + c) = *(const float4*)(kg + go);
            *(float4*)(Vs + r * QK_STRIDE + c) = *(const float4*)(vg + go);
        }
        __syncthreads();

        float s[4][4];
        #pragma unroll
        for (int i = 0; i < 4; i++)
            #pragma unroll
            for (int j = 0; j < 4; j++) s[i][j] = 0.f;
        #pragma unroll 2
        for (int d = 0; d < HD; d += 4) {
            float4 av[4], bv[4];
            #pragma unroll
            for (int i = 0; i < 4; i++)
                av[i] = *(const float4*)(Qs + (ty * 4 + i) * QK_STRIDE + d);
            #pragma unroll
            for (int j = 0; j < 4; j++)
                bv[j] = *(const float4*)(Ks + (tx * 4 + j) * QK_STRIDE + d);
            #pragma unroll
            for (int i = 0; i < 4; i++)
                #pragma unroll
                for (int j = 0; j < 4; j++)
                    s[i][j] += av[i].x * bv[j].x + av[i].y * bv[j].y +
                               av[i].z * bv[j].z + av[i].w * bv[j].w;
        }
        if (kt == qt) {
            #pragma unroll
            for (int i = 0; i < 4; i++)
                #pragma unroll
                for (int j = 0; j < 4; j++)
                    if (tx * 4 + j > ty * 4 + i) s[i][j] = -1e30f;
        }

        #pragma unroll
        for (int i = 0; i < 4; i++) {
            float mm = fmaxf(fmaxf(s[i][0], s[i][1]), fmaxf(s[i][2], s[i][3]));
            mm = fmaxf(mm, __shfl_xor_sync(0xffffffffu, mm, 1));
            mm = fmaxf(mm, __shfl_xor_sync(0xffffffffu, mm, 2));
            mm = fmaxf(mm, __shfl_xor_sync(0xffffffffu, mm, 4));
            mm = fmaxf(mm, __shfl_xor_sync(0xffffffffu, mm, 8));
            float mnew = fmaxf(m_i[i], mm);
            float scl = __expf(m_i[i] - mnew);
            m_i[i] = mnew;
            float rs = 0.f;
            #pragma unroll
            for (int j = 0; j < 4; j++) {
                float p = __expf(s[i][j] - mnew);
                Ps[(ty * 4 + i) * PS_STRIDE + tx * 4 + j] = p;
                rs += p;
            }
            rs += __shfl_xor_sync(0xffffffffu, rs, 1);
            rs += __shfl_xor_sync(0xffffffffu, rs, 2);
            rs += __shfl_xor_sync(0xffffffffu, rs, 4);
            rs += __shfl_xor_sync(0xffffffffu, rs, 8);
            l_i[i] = l_i[i] * scl + rs;
            #pragma unroll
            for (int c = 0; c < 8; c++) acc[i][c] *= scl;
        }
        __syncthreads();

        #pragma unroll 2
        for (int j = 0; j < 64; ++j) {
            float4 v0 = *(const float4*)(Vs + j * QK_STRIDE + tx * 8);
            float4 v1 = *(const float4*)(Vs + j * QK_STRIDE + tx * 8 + 4);
            #pragma unroll
            for (int i = 0; i < 4; i++) {
                float p = Ps[(ty * 4 + i) * PS_STRIDE + j];
                acc[i][0] = fmaf(p, v0.x, acc[i][0]);
                acc[i][1] = fmaf(p, v0.y, acc[i][1]);
                acc[i][2] = fmaf(p, v0.z, acc[i][2]);
                acc[i][3] = fmaf(p, v0.w, acc[i][3]);
                acc[i][4] = fmaf(p, v1.x, acc[i][4]);
                acc[i][5] = fmaf(p, v1.y, acc[i][5]);
                acc[i][6] = fmaf(p, v1.z, acc[i][6]);
                acc[i][7] = fmaf(p, v1.w, acc[i][7]);
            }
        }
    }

    // epilogue: /l, fold Wout column-norm reciprocal, emit bf16 hi/lo
    float ro[8];
    {
        const float* rp = &g_rinv[3][h * HD + tx * 8];
        float4 r0 = *(const float4*)rp;
        float4 r1 = *(const float4*)(rp + 4);
        ro[0] = r0.x; ro[1] = r0.y; ro[2] = r0.z; ro[3] = r0.w;
        ro[4] = r1.x; ro[5] = r1.y; ro[6] = r1.z; ro[7] = r1.w;
    }
    #pragma unroll
    for (int i = 0; i < 4; i++) {
        float inv = 1.f / l_i[i];
        size_t off = (size_t)(qt * 64 + ty * 4 + i) * DI + tx * 8;
        __nv_bfloat162 hh[4], ll[4];
        #pragma unroll
        for (int c = 0; c < 8; c += 2) {
            float v0 = acc[i][c] * inv * ro[c];
            float v1 = acc[i][c + 1] * inv * ro[c + 1];
            __nv_bfloat16 h0 = __float2bfloat16(v0);
            __nv_bfloat16 h1 = __float2bfloat16(v1);
            hh[c >> 1] = __nv_bfloat162(h0, h1);
            ll[c >> 1] = __nv_bfloat162(__float2bfloat16(v0 - __bfloat162float(h0)),
                                        __float2bfloat16(v1 - __bfloat162float(h1)));
        }
        #pragma unroll
        for (int j = 0; j < 4; j++) {
            ((__nv_bfloat162*)(ohp + off))[j] = hh[j];
            ((__nv_bfloat162*)(olp + off))[j] = ll[j];
        }
    }
}

// ============================== host side ====================================
extern "C" void kernel_launch(void* const* d_in, const int* in_sizes, int n_in,
                              void* d_out, int out_size) {
    (void)in_sizes; (void)n_in; (void)out_size;
    const float* x    = (const float*)d_in[0];
    const float* Wq   = (const float*)d_in[1];
    const float* Wk   = (const float*)d_in[2];
    const float* Wv   = (const float*)d_in[3];
    const float* Wout = (const float*)d_in[4];
    const float* qk   = (const float*)d_in[5];
    float* out = (float*)d_out;

    float *pq, *pk, *pv, *pr;
    __nv_bfloat16 *pxh, *pxl, *pwh, *pwl, *poh, *pol;
    cudaGetSymbolAddress((void**)&pq, g_q);
    cudaGetSymbolAddress((void**)&pk, g_k);
    cudaGetSymbolAddress((void**)&pv, g_v);
    cudaGetSymbolAddress((void**)&pr, g_rinv);
    cudaGetSymbolAddress((void**)&pxh, g_xh);
    cudaGetSymbolAddress((void**)&pxl, g_xl);
    cudaGetSymbolAddress((void**)&pwh, g_wh);
    cudaGetSymbolAddress((void**)&pwl, g_wl);
    cudaGetSymbolAddress((void**)&poh, g_oh);
    cudaGetSymbolAddress((void**)&pol, g_ol);

    const size_t WSZ = (size_t)DIM * DIM;

    // 1. converts + fused norms
    convert_x_kernel<<<(MTOT * DIM / 4) / 256, 256>>>(
        (const float4*)x, (__nv_bfloat162*)pxh, (__nv_bfloat162*)pxl);
    convert_w_kernel<<<DIM, 256>>>(Wq, pwh + 0 * WSZ, pwl + 0 * WSZ, 0);
    convert_w_kernel<<<DIM, 256>>>(Wk, pwh + 1 * WSZ, pwl + 1 * WSZ, 1);
    convert_w_kernel<<<DIM, 256>>>(Wv, pwh + 2 * WSZ, pwl + 2 * WSZ, 2);
    convert_wout_kernel<<<(DIM * DIM / 4) / 256, 256>>>(
        (const float4*)Wout, (__nv_bfloat162*)(pwh + 3 * WSZ),
        (__nv_bfloat162*)(pwl + 3 * WSZ));
    colnorm_kernel<<<DIM / 256, 256>>>(Wout);

    // 2. HMMA QKV GEMMs
    const int gsmem = 2 * G_STAGE;   // 64KB
    cudaFuncSetAttribute(hmma_gemm_kernel,
                         cudaFuncAttributeMaxDynamicSharedMemorySize, gsmem);
    dim3 gg(DI / 128, MTOT / 128);   // (16, 32)
    hmma_gemm_kernel<<<gg, 256, gsmem>>>(pxh, pxl, pwh + 0 * WSZ, pwl + 0 * WSZ,
                                         pq, pr + 0 * DIM, DI);
    hmma_gemm_kernel<<<gg, 256, gsmem>>>(pxh, pxl, pwh + 1 * WSZ, pwl + 1 * WSZ,
                                         pk, pr + 1 * DIM, DI);
    hmma_gemm_kernel<<<gg, 256, gsmem>>>(pxh, pxl, pwh + 2 * WSZ, pwl + 2 * WSZ,
                                         pv, pr + 2 * DIM, DI);

    // 3. q/k head norm + scales
    headnorm_kernel<<<(2 * MTOT * HEADS) / 8, 256>>>(qk);

    // 4. attention (emits o as bf16 hi/lo with Wout col-norm folded)
    const size_t asmem = (size_t)(3 * 64 * QK_STRIDE + 64 * PS_STRIDE) * sizeof(float);
    cudaFuncSetAttribute(attn_kernel, cudaFuncAttributeMaxDynamicSharedMemorySize,
                         (int)asmem);
    attn_kernel<<<dim3(SEQ / 64, BATCH * HEADS), 256, asmem>>>();

    // 5. output projection
    hmma_gemm_kernel<<<dim3(DIM / 128, MTOT / 128), 256, gsmem>>>(
        poh, pol, pwh + 3 * WSZ, pwl + 3 * WSZ, out, nullptr, DIM);
}

// round 4
// speedup vs baseline: 2.3066x; 1.7100x over previous
#include <cuda_runtime.h>
#include <cuda_bf16.h>
#include <math.h>
#include <stdint.h>

#define BATCH 2
#define SEQ 2048
#define DIM 2048
#define HEADS 16
#define HD 128
#define DI 2048           /* HEADS*HD */
#define MTOT (BATCH*SEQ)  /* 4096 */

// ---------------- scratch (device globals: allocation-free rule) ------------
__device__ float g_q[(size_t)MTOT * DI];
__device__ float g_k[(size_t)MTOT * DI];
__device__ float g_v[(size_t)MTOT * DI];
__device__ float g_rinv[4][DIM];   // 0:Wq rows, 1:Wk rows, 2:Wv rows, 3:Wout cols

__device__ __nv_bfloat16 g_xh[(size_t)MTOT * DIM];
__device__ __nv_bfloat16 g_xl[(size_t)MTOT * DIM];
__device__ __nv_bfloat16 g_wh[4][(size_t)DIM * DIM];  // q,k,v,out
__device__ __nv_bfloat16 g_wl[4][(size_t)DIM * DIM];
__device__ __nv_bfloat16 g_oh[(size_t)MTOT * DI];
__device__ __nv_bfloat16 g_ol[(size_t)MTOT * DI];

__device__ __nv_bfloat16 g_qh[(size_t)MTOT * DI];
__device__ __nv_bfloat16 g_ql[(size_t)MTOT * DI];
__device__ __nv_bfloat16 g_kh[(size_t)MTOT * DI];
__device__ __nv_bfloat16 g_kl[(size_t)MTOT * DI];
__device__ __nv_bfloat16 g_vh[(size_t)MTOT * DI];
__device__ __nv_bfloat16 g_vl[(size_t)MTOT * DI];

// ============================ PTX helpers (sm_80+ portable) =================
__device__ __forceinline__ uint32_t smem_u32(const void* p) {
    uint32_t a;
    asm("{ .reg .u64 t; cvta.to.shared.u64 t, %1; cvt.u32.u64 %0, t; }"
        : "=r"(a) : "l"(p));
    return a;
}

__device__ __forceinline__ void cp16(uint32_t saddr, const void* g) {
    asm volatile("cp.async.cg.shared.global [%0], [%1], 16;"
                 :: "r"(saddr), "l"(g) : "memory");
}
#define CP_COMMIT() asm volatile("cp.async.commit_group;" ::: "memory")
#define CP_WAIT(n)  asm volatile("cp.async.wait_group %0;" :: "n"(n) : "memory")

#define LDSM_X4(r, addr) \
    asm volatile("ldmatrix.sync.aligned.m8n8.x4.shared.b16 {%0,%1,%2,%3}, [%4];" \
        : "=r"((r)[0]), "=r"((r)[1]), "=r"((r)[2]), "=r"((r)[3]) : "r"(addr))

#define LDSM_X4_T(r, addr) \
    asm volatile("ldmatrix.sync.aligned.m8n8.x4.trans.shared.b16 {%0,%1,%2,%3}, [%4];" \
        : "=r"((r)[0]), "=r"((r)[1]), "=r"((r)[2]), "=r"((r)[3]) : "r"(addr))

#define MMA16816(d, a, b0, b1) \
    asm volatile("mma.sync.aligned.m16n8k16.row.col.f32.bf16.bf16.f32 " \
        "{%0,%1,%2,%3}, {%4,%5,%6,%7}, {%8,%9}, {%0,%1,%2,%3};" \
        : "+f"((d)[0]), "+f"((d)[1]), "+f"((d)[2]), "+f"((d)[3]) \
        : "r"((a)[0]), "r"((a)[1]), "r"((a)[2]), "r"((a)[3]), "r"(b0), "r"(b1))

// split two fp32 into packed bf16 hi (bit-truncation) + bf16 lo (residual, RN)
__device__ __forceinline__ void split2(float a, float b, uint32_t& hi, uint32_t& lo) {
    uint32_t ua = __float_as_uint(a), ub = __float_as_uint(b);
    hi = __byte_perm(ua, ub, 0x7632);   // {lo-half: trunc(a), hi-half: trunc(b)}
    float ra = a - __uint_as_float(ua & 0xFFFF0000u);
    float rb = b - __uint_as_float(ub & 0xFFFF0000u);
    asm("cvt.rn.bf16x2.f32 %0, %1, %2;" : "=r"(lo) : "f"(rb), "f"(ra));
}

// ================= fp32 -> bf16 hi/lo converters (+ fused norms) ============
__global__ void convert_x_kernel(const float4* __restrict__ x,
                                 __nv_bfloat162* __restrict__ hi,
                                 __nv_bfloat162* __restrict__ lo) {
    int i = blockIdx.x * 256 + threadIdx.x;
    float4 v = x[i];
    __nv_bfloat16 h0 = __float2bfloat16(v.x), h1 = __float2bfloat16(v.y);
    __nv_bfloat16 h2 = __float2bfloat16(v.z), h3 = __float2bfloat16(v.w);
    hi[2 * i] = __nv_bfloat162(h0, h1);
    hi[2 * i + 1] = __nv_bfloat162(h2, h3);
    lo[2 * i] = __nv_bfloat162(__float2bfloat16(v.x - __bfloat162float(h0)),
                               __float2bfloat16(v.y - __bfloat162float(h1)));
    lo[2 * i + 1] = __nv_bfloat162(__float2bfloat16(v.z - __bfloat162float(h2)),
                                   __float2bfloat16(v.w - __bfloat162float(h3)));
}

// one block per weight row: convert + row l2 norm reciprocal
__global__ void convert_w_kernel(const float* __restrict__ W,
                                 __nv_bfloat16* __restrict__ hi,
                                 __nv_bfloat16* __restrict__ lo, int sel) {
    __shared__ float red[8];
    const int row = blockIdx.x, tid = threadIdx.x;
    const float4* p = (const float4*)(W + (size_t)row * DIM);
    __nv_bfloat162* hp = (__nv_bfloat162*)(hi + (size_t)row * DIM);
    __nv_bfloat162* lp = (__nv_bfloat162*)(lo + (size_t)row * DIM);
    float s = 0.f;
    #pragma unroll
    for (int i = tid; i < DIM / 4; i += 256) {
        float4 v = p[i];
        s += v.x * v.x + v.y * v.y + v.z * v.z + v.w * v.w;
        __nv_bfloat16 h0 = __float2bfloat16(v.x), h1 = __float2bfloat16(v.y);
        __nv_bfloat16 h2 = __float2bfloat16(v.z), h3 = __float2bfloat16(v.w);
        hp[2 * i] = __nv_bfloat162(h0, h1);
        hp[2 * i + 1] = __nv_bfloat162(h2, h3);
        lp[2 * i] = __nv_bfloat162(__float2bfloat16(v.x - __bfloat162float(h0)),
                                   __float2bfloat16(v.y - __bfloat162float(h1)));
        lp[2 * i + 1] = __nv_bfloat162(__float2bfloat16(v.z - __bfloat162float(h2)),
                                       __float2bfloat16(v.w - __bfloat162float(h3)));
    }
    #pragma unroll
    for (int off = 16; off; off >>= 1) s += __shfl_xor_sync(0xffffffffu, s, off);
    if ((tid & 31) == 0) red[tid >> 5] = s;
    __syncthreads();
    if (tid == 0) {
        float t = 0.f;
        #pragma unroll
        for (int i = 0; i < 8; i++) t += red[i];
        g_rinv[sel][row] = 1.f / fmaxf(sqrtf(t), 1e-12f);
    }
}

// Wout column-norm reciprocal (l2 over dim 0), deterministic serial reduce
__global__ void colnorm_kernel(const float* __restrict__ W) {
    const int col = blockIdx.x * 256 + threadIdx.x;
    float s = 0.f;
    for (int r = 0; r < DIM; ++r) {
        float v = W[(size_t)r * DI + col];
        s += v * v;
    }
    g_rinv[3][col] = 1.f / fmaxf(sqrtf(s), 1e-12f);
}

// =================== HMMA split-bf16 NT GEMM ================================
#define GBM 128
#define GBK 32
#define G_NKT (DIM / GBK)       /* 64 */
#define G_MAT 8192
#define G_STAGE 32768

__global__ void __launch_bounds__(256) hmma_gemm_kernel(
    const __nv_bfloat16* __restrict__ Ahg, const __nv_bfloat16* __restrict__ Alg,
    const __nv_bfloat16* __restrict__ Bhg, const __nv_bfloat16* __restrict__ Blg,
    float* __restrict__ C, const float* __restrict__ rinv, int ldc)
{
    extern __shared__ char smem[];
    const uint32_t sb = smem_u32(smem);
    const int tid = threadIdx.x;
    const int wid = tid >> 5, lane = tid & 31;
    const int wm = wid & 3, wn = wid >> 2;
    const int mbase = blockIdx.y * GBM;
    const int nbase = blockIdx.x * GBM;

    auto load_stage = [&](int kt, int buf) {
        const uint32_t st = sb + buf * G_STAGE;
        const int koff = kt * GBK;
        #pragma unroll
        for (int half = 0; half < 2; ++half) {
            const int cid = tid + half * 256;
            const int r = cid >> 2, c = cid & 3;
            const uint32_t aoff = ((c >> 1) << 12) + ((r >> 4) << 9) +
                (((r & 7) + ((r >> 3) & 1) * 8 + (c & 1) * 16) << 4);
            const uint32_t boff = ((c >> 1) << 12) + ((r >> 4) << 9) +
                (((r & 7) + (c & 1) * 8 + ((r >> 3) & 1) * 16) << 4);
            const size_t ga = (size_t)(mbase + r) * DIM + koff + c * 8;
            const size_t gb = (size_t)(nbase + r) * DIM + koff + c * 8;
            cp16(st + aoff, Ahg + ga);
            cp16(st + G_MAT + aoff, Alg + ga);
            cp16(st + 2 * G_MAT + boff, Bhg + gb);
            cp16(st + 3 * G_MAT + boff, Blg + gb);
        }
    };

    float acc[2][8][4];
    #pragma unroll
    for (int i = 0; i < 2; i++)
        #pragma unroll
        for (int j = 0; j < 8; j++)
            #pragma unroll
            for (int t = 0; t < 4; t++) acc[i][j][t] = 0.f;

    load_stage(0, 0); CP_COMMIT();
    load_stage(1, 1); CP_COMMIT();
    CP_WAIT(1);
    __syncthreads();

    for (int kt = 0; kt < G_NKT; ++kt) {
        const int buf = kt & 1;
        const uint32_t stg = sb + buf * G_STAGE;
        #pragma unroll
        for (int s = 0; s < 2; ++s) {
            const uint32_t aAddr = stg + (s << 12) + ((wm * 2) << 9) + lane * 16;
            const uint32_t bAddr = stg + 2 * G_MAT + (s << 12) + ((wn * 4) << 9) + lane * 16;
            uint32_t ah0[4], ah1[4], al0[4], al1[4], b[4][4];
            LDSM_X4(ah0, aAddr);
            LDSM_X4(ah1, aAddr + 512);
            LDSM_X4(al0, aAddr + G_MAT);
            LDSM_X4(al1, aAddr + G_MAT + 512);
            #pragma unroll
            for (int jt = 0; jt < 4; ++jt) LDSM_X4(b[jt], bAddr + jt * 512);
            #pragma unroll
            for (int jt = 0; jt < 4; ++jt) {
                MMA16816(acc[0][2 * jt],     ah0, b[jt][0], b[jt][1]);
                MMA16816(acc[0][2 * jt + 1], ah0, b[jt][2], b[jt][3]);
                MMA16816(acc[1][2 * jt],     ah1, b[jt][0], b[jt][1]);
                MMA16816(acc[1][2 * jt + 1], ah1, b[jt][2], b[jt][3]);
                MMA16816(acc[0][2 * jt],     al0, b[jt][0], b[jt][1]);
                MMA16816(acc[0][2 * jt + 1], al0, b[jt][2], b[jt][3]);
                MMA16816(acc[1][2 * jt],     al1, b[jt][0], b[jt][1]);
                MMA16816(acc[1][2 * jt + 1], al1, b[jt][2], b[jt][3]);
            }
            #pragma unroll
            for (int jt = 0; jt < 4; ++jt) LDSM_X4(b[jt], bAddr + G_MAT + jt * 512);
            #pragma unroll
            for (int jt = 0; jt < 4; ++jt) {
                MMA16816(acc[0][2 * jt],     ah0, b[jt][0], b[jt][1]);
                MMA16816(acc[0][2 * jt + 1], ah0, b[jt][2], b[jt][3]);
                MMA16816(acc[1][2 * jt],     ah1, b[jt][0], b[jt][1]);
                MMA16816(acc[1][2 * jt + 1], ah1, b[jt][2], b[jt][3]);
            }
        }
        __syncthreads();
        if (kt + 2 < G_NKT) {
            load_stage(kt + 2, buf);
            CP_COMMIT();
            CP_WAIT(1);
        } else {
            CP_WAIT(0);
        }
        __syncthreads();
    }

    const int r0 = mbase + wm * 32 + (lane >> 2);
    #pragma unroll
    for (int j = 0; j < 8; ++j) {
        const int col = nbase + wn * 64 + j * 8 + (lane & 3) * 2;
        const float s0 = rinv ? rinv[col] : 1.f;
        const float s1 = rinv ? rinv[col + 1] : 1.f;
        #pragma unroll
        for (int i = 0; i < 2; ++i) {
            const int row = r0 + i * 16;
            float2 d0 = make_float2(acc[i][j][0] * s0, acc[i][j][1] * s1);
            float2 d1 = make_float2(acc[i][j][2] * s0, acc[i][j][3] * s1);
            *(float2*)(C + (size_t)row * ldc + col) = d0;
            *(float2*)(C + (size_t)(row + 8) * ldc + col) = d1;
        }
    }
}

// ------- per-head l2norm of q,k + fold qk_scale*DIM*sqrt(HD); emit bf16 hi/lo
__global__ void headnorm_kernel(const float* __restrict__ qk_scale) {
    const int w = blockIdx.x * 8 + (threadIdx.x >> 5);
    const int lane = threadIdx.x & 31;
    const int tensor = w >> 16;              // 0:q 1:k
    const int v = w & 65535;                 // (b*SEQ+n)*HEADS + h
    const int h = v & 15;
    const size_t off = (size_t)(v >> 4) * DI + (size_t)h * HD + lane * 4;
    const float* src = (tensor ? g_k : g_q) + off;
    __nv_bfloat162* dh = (__nv_bfloat162*)((tensor ? g_kh : g_qh) + off);
    __nv_bfloat162* dl = (__nv_bfloat162*)((tensor ? g_kl : g_ql) + off);
    float4 x = *(const float4*)src;
    float ss = x.x * x.x + x.y * x.y + x.z * x.z + x.w * x.w;
    #pragma unroll
    for (int o = 16; o; o >>= 1) ss += __shfl_xor_sync(0xffffffffu, ss, o);
    float rinv = 1.f / fmaxf(sqrtf(ss), 1e-12f);
    if (tensor == 0) {
        const float mul = 2048.0f * 11.313708498984761f;   // DIM * sqrt(HD)
        const float* s4 = qk_scale + (size_t)h * HD + lane * 4;
        x.x *= rinv * s4[0] * mul;
        x.y *= rinv * s4[1] * mul;
        x.z *= rinv * s4[2] * mul;
        x.w *= rinv * s4[3] * mul;
    } else {
        x.x *= rinv; x.y *= rinv; x.z *= rinv; x.w *= rinv;
    }
    __nv_bfloat16 h0 = __float2bfloat16(x.x), h1 = __float2bfloat16(x.y);
    __nv_bfloat16 h2 = __float2bfloat16(x.z), h3 = __float2bfloat16(x.w);
    dh[0] = __nv_bfloat162(h0, h1);
    dh[1] = __nv_bfloat162(h2, h3);
    dl[0] = __nv_bfloat162(__float2bfloat16(x.x - __bfloat162float(h0)),
                           __float2bfloat16(x.y - __bfloat162float(h1)));
    dl[1] = __nv_bfloat162(__float2bfloat16(x.z - __bfloat162float(h2)),
                           __float2bfloat16(x.w - __bfloat162float(h3)));
}

// =================== HMMA split-bf16 causal flash attention ==================
// 64x64 tiles, 128 thr / 4 warps, warp = 16 Q rows. All tiles 64x256B swizzled.
#define AQH 0
#define AQL 16384
#define AKH 32768
#define AKL 49152
#define AVH 65536
#define AVL 81920
#define A_SMEM 98304

__global__ void __launch_bounds__(128) attn_hmma_kernel() {
    extern __shared__ char asmembuf[];
    const uint32_t sb = smem_u32(asmembuf);
    const int tid = threadIdx.x;
    const int wid = tid >> 5, lane = tid & 31;
    const int qt = 31 - blockIdx.x;         // longest work first
    const int bh = blockIdx.y;
    const int b = bh >> 4, h = bh & 15;
    const size_t base = (size_t)b * SEQ * DI + (size_t)h * HD;
    const __nv_bfloat16 *qhp = g_qh + base, *qlp = g_ql + base;
    const __nv_bfloat16 *khp = g_kh + base, *klp = g_kl + base;
    const __nv_bfloat16 *vhp = g_vh + base, *vlp = g_vl + base;

    // load Q tiles (hi/lo), swizzled chunk = c ^ (r&7)
    #pragma unroll
    for (int it = 0; it < 8; ++it) {
        const int i = tid + it * 128;
        const int r = i >> 4, c = i & 15;
        const size_t g = (size_t)(qt * 64 + r) * DI + c * 8;
        const uint32_t s = (r << 8) + ((c ^ (r & 7)) << 4);
        cp16(sb + AQH + s, qhp + g);
        cp16(sb + AQL + s, qlp + g);
    }
    CP_COMMIT();

    float oAcc[16][4];
    #pragma unroll
    for (int i = 0; i < 16; i++)
        #pragma unroll
        for (int j = 0; j < 4; j++) oAcc[i][j] = 0.f;
    float m0 = -1e30f, m1 = -1e30f, l0 = 0.f, l1 = 0.f;

    for (int kt = 0; kt <= qt; ++kt) {
        // load K/V tiles (hi/lo)
        #pragma unroll
        for (int it = 0; it < 8; ++it) {
            const int i = tid + it * 128;
            const int r = i >> 4, c = i & 15;
            const size_t g = (size_t)(kt * 64 + r) * DI + c * 8;
            const uint32_t s = (r << 8) + ((c ^ (r & 7)) << 4);
            cp16(sb + AKH + s, khp + g);
            cp16(sb + AKL + s, klp + g);
            cp16(sb + AVH + s, vhp + g);
            cp16(sb + AVL + s, vlp + g);
        }
        CP_COMMIT(); CP_WAIT(0);
        __syncthreads();

        // ---- S = Q K^T (3-pass split) ----
        float sAcc[8][4];
        #pragma unroll
        for (int i = 0; i < 8; i++)
            #pragma unroll
            for (int j = 0; j < 4; j++) sAcc[i][j] = 0.f;

        #pragma unroll
        for (int kk = 0; kk < 8; ++kk) {
            const int arow = wid * 16 + (lane & 15);
            const int achk = 2 * kk + (lane >> 4);
            const uint32_t aoff = (arow << 8) + ((achk ^ (arow & 7)) << 4);
            uint32_t qh[4], ql[4];
            LDSM_X4(qh, sb + AQH + aoff);
            LDSM_X4(ql, sb + AQL + aoff);
            const int brow_ = (lane & 7) + ((lane >> 4) & 1) * 8;
            const int bchk = 2 * kk + ((lane >> 3) & 1);
            #pragma unroll
            for (int g = 0; g < 4; ++g) {
                const int brow = g * 16 + brow_;
                const uint32_t boff = (brow << 8) + ((bchk ^ (brow & 7)) << 4);
                uint32_t kh[4], kl[4];
                LDSM_X4(kh, sb + AKH + boff);
                LDSM_X4(kl, sb + AKL + boff);
                MMA16816(sAcc[2 * g],     qh, kh[0], kh[1]);
                MMA16816(sAcc[2 * g + 1], qh, kh[2], kh[3]);
                MMA16816(sAcc[2 * g],     qh, kl[0], kl[1]);
                MMA16816(sAcc[2 * g + 1], qh, kl[2], kl[3]);
                MMA16816(sAcc[2 * g],     ql, kh[0], kh[1]);
                MMA16816(sAcc[2 * g + 1], ql, kh[2], kh[3]);
            }
        }

        // ---- causal mask on diagonal tile ----
        if (kt == qt) {
            const int colb = (lane & 3) * 2;
            const int rowa = wid * 16 + (lane >> 2);
            #pragma unroll
            for (int jt = 0; jt < 8; ++jt) {
                const int c0 = jt * 8 + colb;
                if (c0 > rowa)     sAcc[jt][0] = -1e30f;
                if (c0 + 1 > rowa) sAcc[jt][1] = -1e30f;
                if (c0 > rowa + 8)     sAcc[jt][2] = -1e30f;
                if (c0 + 1 > rowa + 8) sAcc[jt][3] = -1e30f;
            }
        }

        // ---- online softmax (rows r0 = lane>>2, r1 = r0+8) ----
        float mx0 = -1e30f, mx1 = -1e30f;
        #pragma unroll
        for (int jt = 0; jt < 8; ++jt) {
            mx0 = fmaxf(mx0, fmaxf(sAcc[jt][0], sAcc[jt][1]));
            mx1 = fmaxf(mx1, fmaxf(sAcc[jt][2], sAcc[jt][3]));
        }
        mx0 = fmaxf(mx0, __shfl_xor_sync(0xffffffffu, mx0, 1));
        mx0 = fmaxf(mx0, __shfl_xor_sync(0xffffffffu, mx0, 2));
        mx1 = fmaxf(mx1, __shfl_xor_sync(0xffffffffu, mx1, 1));
        mx1 = fmaxf(mx1, __shfl_xor_sync(0xffffffffu, mx1, 2));
        const float mn0 = fmaxf(m0, mx0), mn1 = fmaxf(m1, mx1);
        const float scl0 = __expf(m0 - mn0), scl1 = __expf(m1 - mn1);
        m0 = mn0; m1 = mn1;

        uint32_t ph[8][2], pl[8][2];
        float rs0 = 0.f, rs1 = 0.f;
        #pragma unroll
        for (int jt = 0; jt < 8; ++jt) {
            const float p0 = __expf(sAcc[jt][0] - mn0);
            const float p1 = __expf(sAcc[jt][1] - mn0);
            const float p2 = __expf(sAcc[jt][2] - mn1);
            const float p3 = __expf(sAcc[jt][3] - mn1);
            rs0 += p0 + p1;
            rs1 += p2 + p3;
            split2(p0, p1, ph[jt][0], pl[jt][0]);
            split2(p2, p3, ph[jt][1], pl[jt][1]);
        }
        rs0 += __shfl_xor_sync(0xffffffffu, rs0, 1);
        rs0 += __shfl_xor_sync(0xffffffffu, rs0, 2);
        rs1 += __shfl_xor_sync(0xffffffffu, rs1, 1);
        rs1 += __shfl_xor_sync(0xffffffffu, rs1, 2);
        l0 = l0 * scl0 + rs0;
        l1 = l1 * scl1 + rs1;
        #pragma unroll
        for (int dt = 0; dt < 16; ++dt) {
            oAcc[dt][0] *= scl0; oAcc[dt][1] *= scl0;
            oAcc[dt][2] *= scl1; oAcc[dt][3] *= scl1;
        }

        // ---- O += P V (3-pass split), V via ldmatrix.trans ----
        #pragma unroll
        for (int t = 0; t < 4; ++t) {
            uint32_t pa[4] = {ph[2 * t][0], ph[2 * t][1], ph[2 * t + 1][0], ph[2 * t + 1][1]};
            uint32_t pb[4] = {pl[2 * t][0], pl[2 * t][1], pl[2 * t + 1][0], pl[2 * t + 1][1]};
            const int vrow = t * 16 + (lane & 7) + ((lane >> 3) & 1) * 8;
            #pragma unroll
            for (int g = 0; g < 8; ++g) {
                const int vchk = 2 * g + (lane >> 4);
                const uint32_t voff = (vrow << 8) + ((vchk ^ (vrow & 7)) << 4);
                uint32_t vh[4], vl[4];
                LDSM_X4_T(vh, sb + AVH + voff);
                LDSM_X4_T(vl, sb + AVL + voff);
                MMA16816(oAcc[2 * g],     pa, vh[0], vh[1]);
                MMA16816(oAcc[2 * g + 1], pa, vh[2], vh[3]);
                MMA16816(oAcc[2 * g],     pa, vl[0], vl[1]);
                MMA16816(oAcc[2 * g + 1], pa, vl[2], vl[3]);
                MMA16816(oAcc[2 * g],     pb, vh[0], vh[1]);
                MMA16816(oAcc[2 * g + 1], pb, vh[2], vh[3]);
            }
        }
        __syncthreads();
    }

    // ---- epilogue: /l, fold Wout col-norm, emit bf16 hi/lo ----
    const float li0 = 1.f / l0, li1 = 1.f / l1;
    const int row0 = qt * 64 + wid * 16 + (lane >> 2);
    const int colb = (lane & 3) * 2;
    __nv_bfloat16* ohp = g_oh + base;
    __nv_bfloat16* olp = g_ol + base;
    #pragma unroll
    for (int dt = 0; dt < 16; ++dt) {
        const int d = dt * 8 + colb;
        const float2 ro = *(const float2*)&g_rinv[3][h * HD + d];
        const float v0 = oAcc[dt][0] * li0 * ro.x;
        const float v1 = oAcc[dt][1] * li0 * ro.y;
        const float v2 = oAcc[dt][2] * li1 * ro.x;
        const float v3 = oAcc[dt][3] * li1 * ro.y;
        uint32_t hi0, lo0, hi1, lo1;
        split2(v0, v1, hi0, lo0);
        split2(v2, v3, hi1, lo1);
        const size_t o0 = (size_t)row0 * DI + d;
        const size_t o1 = (size_t)(row0 + 8) * DI + d;
        *(uint32_t*)(ohp + o0) = hi0;
        *(uint32_t*)(olp + o0) = lo0;
        *(uint32_t*)(ohp + o1) = hi1;
        *(uint32_t*)(olp + o1) = lo1;
    }
}

// ============================== host side ====================================
extern "C" void kernel_launch(void* const* d_in, const int* in_sizes, int n_in,
                              void* d_out, int out_size) {
    (void)in_sizes; (void)n_in; (void)out_size;
    const float* x    = (const float*)d_in[0];
    const float* Wq   = (const float*)d_in[1];
    const float* Wk   = (const float*)d_in[2];
    const float* Wv   = (const float*)d_in[3];
    const float* Wout = (const float*)d_in[4];
    const float* qk   = (const float*)d_in[5];
    float* out = (float*)d_out;

    float *pq, *pk, *pv, *pr;
    __nv_bfloat16 *pxh, *pxl, *pwh, *pwl, *poh, *pol, *pvh, *pvl;
    cudaGetSymbolAddress((void**)&pq, g_q);
    cudaGetSymbolAddress((void**)&pk, g_k);
    cudaGetSymbolAddress((void**)&pv, g_v);
    cudaGetSymbolAddress((void**)&pr, g_rinv);
    cudaGetSymbolAddress((void**)&pxh, g_xh);
    cudaGetSymbolAddress((void**)&pxl, g_xl);
    cudaGetSymbolAddress((void**)&pwh, g_wh);
    cudaGetSymbolAddress((void**)&pwl, g_wl);
    cudaGetSymbolAddress((void**)&poh, g_oh);
    cudaGetSymbolAddress((void**)&pol, g_ol);
    cudaGetSymbolAddress((void**)&pvh, g_vh);
    cudaGetSymbolAddress((void**)&pvl, g_vl);

    const size_t WSZ = (size_t)DIM * DIM;
    const int gsmem = 2 * G_STAGE;   // 64KB
    cudaFuncSetAttribute(hmma_gemm_kernel,
                         cudaFuncAttributeMaxDynamicSharedMemorySize, gsmem);
    cudaFuncSetAttribute(attn_hmma_kernel,
                         cudaFuncAttributeMaxDynamicSharedMemorySize, A_SMEM);
    dim3 gg(DI / 128, MTOT / 128);   // (16, 32)

    // launches 0-3: converts needed for QKV GEMMs
    convert_x_kernel<<<(MTOT * DIM / 4) / 256, 256>>>(
        (const float4*)x, (__nv_bfloat162*)pxh, (__nv_bfloat162*)pxl);
    convert_w_kernel<<<DIM, 256>>>(Wq, pwh + 0 * WSZ, pwl + 0 * WSZ, 0);
    convert_w_kernel<<<DIM, 256>>>(Wk, pwh + 1 * WSZ, pwl + 1 * WSZ, 1);
    convert_w_kernel<<<DIM, 256>>>(Wv, pwh + 2 * WSZ, pwl + 2 * WSZ, 2);

    // launches 4-6: QKV GEMMs (launch 5 = K GEMM is what ncu -s 5 captures)
    hmma_gemm_kernel<<<gg, 256, gsmem>>>(pxh, pxl, pwh + 0 * WSZ, pwl + 0 * WSZ,
                                         pq, pr + 0 * DIM, DI);
    hmma_gemm_kernel<<<gg, 256, gsmem>>>(pxh, pxl, pwh + 1 * WSZ, pwl + 1 * WSZ,
                                         pk, pr + 1 * DIM, DI);
    hmma_gemm_kernel<<<gg, 256, gsmem>>>(pxh, pxl, pwh + 2 * WSZ, pwl + 2 * WSZ,
                                         pv, pr + 2 * DIM, DI);

    // launches 7-8: Wout convert + column norm
    convert_x_kernel<<<(DIM * DIM / 4) / 256, 256>>>(
        (const float4*)Wout, (__nv_bfloat162*)(pwh + 3 * WSZ),
        (__nv_bfloat162*)(pwl + 3 * WSZ));
    colnorm_kernel<<<DIM / 256, 256>>>(Wout);

    // launches 9-10: head norms (q,k -> bf16 hi/lo), v split
    headnorm_kernel<<<(2 * MTOT * HEADS) / 8, 256>>>(qk);
    convert_x_kernel<<<(MTOT * DI / 4) / 256, 256>>>(
        (const float4*)pv, (__nv_bfloat162*)pvh, (__nv_bfloat162*)pvl);

    // launch 11: HMMA flash attention (emits o bf16 hi/lo, Wout norm folded)
    attn_hmma_kernel<<<dim3(SEQ / 64, BATCH * HEADS), 128, A_SMEM>>>();

    // launch 12: output projection
    hmma_gemm_kernel<<<dim3(DIM / 128, MTOT / 128), 256, gsmem>>>(
        poh, pol, pwh + 3 * WSZ, pwl + 3 * WSZ, out, nullptr, DIM);
}

// round 6
// speedup vs baseline: 3.5698x; 1.5476x over previous
#include <cuda_runtime.h>
#include <cuda_fp16.h>
#include <math.h>
#include <stdint.h>

#define BATCH 2
#define SEQ 2048
#define DIM 2048
#define HEADS 16
#define HD 128
#define DI 2048           /* HEADS*HD */
#define MTOT (BATCH*SEQ)  /* 4096 */

// ---------------- scratch (device globals: allocation-free rule) ------------
__device__ float g_rinv[4][DIM];     // 0:Wq rows 1:Wk rows 2:Wv rows 3:Wout cols
__device__ float g_colpart[16][DIM];
__device__ __half g_xh[(size_t)MTOT * DIM];
__device__ __half g_xl[(size_t)MTOT * DIM];
__device__ __half g_w16[4][(size_t)DIM * DIM];   // q,k,v,out (single fp16)
__device__ __half g_qh[(size_t)MTOT * DI];
__device__ __half g_ql[(size_t)MTOT * DI];
__device__ __half g_k16[(size_t)MTOT * DI];
__device__ __half g_v16[(size_t)MTOT * DI];
__device__ __half g_oh[(size_t)MTOT * DI];
__device__ __half g_ol[(size_t)MTOT * DI];

// ============================ PTX helpers (sm_80+ portable) =================
__device__ __forceinline__ uint32_t smem_u32(const void* p) {
    uint32_t a;
    asm("{ .reg .u64 t; cvta.to.shared.u64 t, %1; cvt.u32.u64 %0, t; }"
        : "=r"(a) : "l"(p));
    return a;
}

__device__ __forceinline__ void cp16(uint32_t saddr, const void* g) {
    asm volatile("cp.async.cg.shared.global [%0], [%1], 16;"
                 :: "r"(saddr), "l"(g) : "memory");
}
#define CP_COMMIT() asm volatile("cp.async.commit_group;" ::: "memory")
#define CP_WAIT(n)  asm volatile("cp.async.wait_group %0;" :: "n"(n) : "memory")

#define LDSM_X4(r, addr) \
    asm volatile("ldmatrix.sync.aligned.m8n8.x4.shared.b16 {%0,%1,%2,%3}, [%4];" \
        : "=r"((r)[0]), "=r"((r)[1]), "=r"((r)[2]), "=r"((r)[3]) : "r"(addr))

#define LDSM_X4_T(r, addr) \
    asm volatile("ldmatrix.sync.aligned.m8n8.x4.trans.shared.b16 {%0,%1,%2,%3}, [%4];" \
        : "=r"((r)[0]), "=r"((r)[1]), "=r"((r)[2]), "=r"((r)[3]) : "r"(addr))

#define MMA16816H(d, a, b0, b1) \
    asm volatile("mma.sync.aligned.m16n8k16.row.col.f32.f16.f16.f32 " \
        "{%0,%1,%2,%3}, {%4,%5,%6,%7}, {%8,%9}, {%0,%1,%2,%3};" \
        : "+f"((d)[0]), "+f"((d)[1]), "+f"((d)[2]), "+f"((d)[3]) \
        : "r"((a)[0]), "r"((a)[1]), "r"((a)[2]), "r"((a)[3]), "r"(b0), "r"(b1))

__device__ __forceinline__ uint32_t pack2h(float a, float b) {
    uint32_t r;
    asm("cvt.rn.f16x2.f32 %0, %1, %2;" : "=r"(r) : "f"(b), "f"(a));
    return r;
}
// split (a,b) into packed fp16 hi + fp16 residual lo
__device__ __forceinline__ void splith2(float a, float b, uint32_t& hi, uint32_t& lo) {
    hi = pack2h(a, b);
    __half2 h = *(__half2*)&hi;
    lo = pack2h(a - __half2float(__low2half(h)),
                b - __half2float(__high2half(h)));
}

// ================= fp32 -> fp16 converters (+ fused norms) ==================
__global__ void convert_x16(const float4* __restrict__ x,
                            uint32_t* __restrict__ hi, uint32_t* __restrict__ lo) {
    int i = blockIdx.x * 256 + threadIdx.x;
    float4 v = x[i];
    uint32_t h0, l0, h1, l1;
    splith2(v.x, v.y, h0, l0);
    splith2(v.z, v.w, h1, l1);
    hi[2 * i] = h0; hi[2 * i + 1] = h1;
    lo[2 * i] = l0; lo[2 * i + 1] = l1;
}

// one block per weight row: single fp16 convert + row l2 norm reciprocal
__global__ void convert_w16(const float* __restrict__ W,
                            __half* __restrict__ o, int sel) {
    __shared__ float red[8];
    const int row = blockIdx.x, tid = threadIdx.x;
    const float4* p = (const float4*)(W + (size_t)row * DIM);
    uint32_t* op = (uint32_t*)(o + (size_t)row * DIM);
    float s = 0.f;
    #pragma unroll
    for (int i = tid; i < DIM / 4; i += 256) {
        float4 v = p[i];
        s += v.x * v.x + v.y * v.y + v.z * v.z + v.w * v.w;
        op[2 * i] = pack2h(v.x, v.y);
        op[2 * i + 1] = pack2h(v.z, v.w);
    }
    #pragma unroll
    for (int off = 16; off; off >>= 1) s += __shfl_xor_sync(0xffffffffu, s, off);
    if ((tid & 31) == 0) red[tid >> 5] = s;
    __syncthreads();
    if (tid == 0) {
        float t = 0.f;
        #pragma unroll
        for (int i = 0; i < 8; i++) t += red[i];
        g_rinv[sel][row] = 1.f / fmaxf(sqrtf(t), 1e-12f);
    }
}

__global__ void convert_flat16(const float4* __restrict__ W, uint32_t* __restrict__ o) {
    int i = blockIdx.x * 256 + threadIdx.x;
    float4 v = W[i];
    o[2 * i] = pack2h(v.x, v.y);
    o[2 * i + 1] = pack2h(v.z, v.w);
}

// Wout column-norm: two-phase deterministic parallel reduce
__global__ void colnorm_part(const float* __restrict__ W) {
    const int col = blockIdx.x * 256 + threadIdx.x;
    const int r0 = blockIdx.y * 128;
    float s = 0.f;
    for (int r = 0; r < 128; ++r) {
        float v = W[(size_t)(r0 + r) * DI + col];
        s += v * v;
    }
    g_colpart[blockIdx.y][col] = s;
}
__global__ void colnorm_fin() {
    int c = blockIdx.x * 256 + threadIdx.x;
    float s = 0.f;
    #pragma unroll
    for (int i = 0; i < 16; ++i) s += g_colpart[i][c];
    g_rinv[3][c] = 1.f / fmaxf(sqrtf(s), 1e-12f);
}

// =================== fp16 2-pass NT GEMM (split A, single B) =================
// C[m,n] = sum_k A[m,k]*B[n,k]; 128x128x32 CTA tile, 3-stage cp.async.
// MODE 0: fp32 out (*rinv if set)      MODE 1: *rinv -> fp16 out (v)
// MODE 2: *rinv, headnorm, *qks*DIM*sqrt(HD) -> fp16 hi/lo (q)
// MODE 3: *rinv, headnorm -> fp16 out (k)
#define GS_MAT 8192
#define GS_STAGE 24576
#define GS_NKT (DIM / 32)   /* 64 */

template<int MODE>
__global__ void __launch_bounds__(256) gemm16(
    const __half* __restrict__ Ahg, const __half* __restrict__ Alg,
    const __half* __restrict__ Bg,
    float* __restrict__ Cf, __half* __restrict__ Ch, __half* __restrict__ Cl,
    const float* __restrict__ rinv, const float* __restrict__ qks, int ldc)
{
    extern __shared__ char smem[];
    const uint32_t sb = smem_u32(smem);
    const int tid = threadIdx.x;
    const int wid = tid >> 5, lane = tid & 31;
    const int wm = wid & 3, wn = wid >> 2;
    const int mbase = blockIdx.y * 128, nbase = blockIdx.x * 128;

    auto load_stage = [&](int kt, int buf) {
        const uint32_t st = sb + buf * GS_STAGE;
        const int koff = kt * 32;
        #pragma unroll
        for (int h = 0; h < 2; ++h) {
            const int cid = tid + h * 256;
            const int r = cid >> 2, c = cid & 3;
            const uint32_t aoff = ((c >> 1) << 12) + ((r >> 4) << 9) +
                (((r & 7) + ((r >> 3) & 1) * 8 + (c & 1) * 16) << 4);
            const uint32_t boff = ((c >> 1) << 12) + ((r >> 4) << 9) +
                (((r & 7) + (c & 1) * 8 + ((r >> 3) & 1) * 16) << 4);
            const size_t ga = (size_t)(mbase + r) * DIM + koff + c * 8;
            cp16(st + aoff, Ahg + ga);
            cp16(st + GS_MAT + aoff, Alg + ga);
            cp16(st + 2 * GS_MAT + boff, Bg + (size_t)(nbase + r) * DIM + koff + c * 8);
        }
    };

    float acc[2][8][4];
    #pragma unroll
    for (int i = 0; i < 2; i++)
        #pragma unroll
        for (int j = 0; j < 8; j++)
            #pragma unroll
            for (int t = 0; t < 4; t++) acc[i][j][t] = 0.f;

    load_stage(0, 0); CP_COMMIT();
    load_stage(1, 1); CP_COMMIT();

    for (int kt = 0; kt < GS_NKT; ++kt) {
        CP_WAIT(1);          // oldest real group (kt) complete
        __syncthreads();     // everyone's data visible; compute(kt-1) done
        if (kt + 2 < GS_NKT) load_stage(kt + 2, (kt + 2) % 3);
        CP_COMMIT();         // always commit (empty ok) to keep wait semantics
        const uint32_t stg = sb + (kt % 3) * GS_STAGE;
        #pragma unroll
        for (int s = 0; s < 2; ++s) {
            const uint32_t aA = stg + (s << 12) + ((wm * 2) << 9) + lane * 16;
            const uint32_t bA = stg + 2 * GS_MAT + (s << 12) + ((wn * 4) << 9) + lane * 16;
            uint32_t ah0[4], ah1[4], al0[4], al1[4], b[4][4];
            LDSM_X4(ah0, aA);
            LDSM_X4(ah1, aA + 512);
            LDSM_X4(al0, aA + GS_MAT);
            LDSM_X4(al1, aA + GS_MAT + 512);
            #pragma unroll
            for (int jt = 0; jt < 4; ++jt) LDSM_X4(b[jt], bA + jt * 512);
            #pragma unroll
            for (int jt = 0; jt < 4; ++jt) {
                MMA16816H(acc[0][2 * jt],     ah0, b[jt][0], b[jt][1]);
                MMA16816H(acc[0][2 * jt + 1], ah0, b[jt][2], b[jt][3]);
                MMA16816H(acc[1][2 * jt],     ah1, b[jt][0], b[jt][1]);
                MMA16816H(acc[1][2 * jt + 1], ah1, b[jt][2], b[jt][3]);
                MMA16816H(acc[0][2 * jt],     al0, b[jt][0], b[jt][1]);
                MMA16816H(acc[0][2 * jt + 1], al0, b[jt][2], b[jt][3]);
                MMA16816H(acc[1][2 * jt],     al1, b[jt][0], b[jt][1]);
                MMA16816H(acc[1][2 * jt + 1], al1, b[jt][2], b[jt][3]);
            }
        }
    }
    __syncthreads();

    // -------- epilogue --------
    const int lr0 = wm * 32 + (lane >> 2);
    if (rinv) {
        #pragma unroll
        for (int j = 0; j < 8; ++j) {
            const int col = nbase + wn * 64 + j * 8 + (lane & 3) * 2;
            const float s0 = rinv[col], s1 = rinv[col + 1];
            #pragma unroll
            for (int i = 0; i < 2; ++i) {
                acc[i][j][0] *= s0; acc[i][j][1] *= s1;
                acc[i][j][2] *= s0; acc[i][j][3] *= s1;
            }
        }
    }
    if (MODE == 2 || MODE == 3) {
        // per-row l2 norm over this CTA's 128 cols (= one head)
        float ssq[4] = {0.f, 0.f, 0.f, 0.f};
        #pragma unroll
        for (int i = 0; i < 2; ++i)
            #pragma unroll
            for (int j = 0; j < 8; ++j) {
                ssq[2 * i]     += acc[i][j][0] * acc[i][j][0] + acc[i][j][1] * acc[i][j][1];
                ssq[2 * i + 1] += acc[i][j][2] * acc[i][j][2] + acc[i][j][3] * acc[i][j][3];
            }
        #pragma unroll
        for (int r = 0; r < 4; ++r) {
            ssq[r] += __shfl_xor_sync(0xffffffffu, ssq[r], 1);
            ssq[r] += __shfl_xor_sync(0xffffffffu, ssq[r], 2);
        }
        float* red = (float*)smem;   // reuse pipeline smem: [2][128]
        if ((lane & 3) == 0) {
            #pragma unroll
            for (int r = 0; r < 4; ++r)
                red[wn * 128 + lr0 + (r & 1) * 8 + (r >> 1) * 16] = ssq[r];
        }
        __syncthreads();
        float rn_[4];
        #pragma unroll
        for (int r = 0; r < 4; ++r) {
            const int lr = lr0 + (r & 1) * 8 + (r >> 1) * 16;
            rn_[r] = 1.f / fmaxf(sqrtf(red[lr] + red[128 + lr]), 1e-12f);
        }
        #pragma unroll
        for (int i = 0; i < 2; ++i)
            #pragma unroll
            for (int j = 0; j < 8; ++j) {
                acc[i][j][0] *= rn_[2 * i];     acc[i][j][1] *= rn_[2 * i];
                acc[i][j][2] *= rn_[2 * i + 1]; acc[i][j][3] *= rn_[2 * i + 1];
            }
    }
    #pragma unroll
    for (int j = 0; j < 8; ++j) {
        const int col = nbase + wn * 64 + j * 8 + (lane & 3) * 2;
        float qm0 = 1.f, qm1 = 1.f;
        if (MODE == 2) {
            qm0 = qks[col] * 23170.475005920826f;      // DIM * sqrt(HD)
            qm1 = qks[col + 1] * 23170.475005920826f;
        }
        #pragma unroll
        for (int i = 0; i < 2; ++i) {
            const int row = mbase + lr0 + i * 16;
            if (MODE == 0) {
                *(float2*)(Cf + (size_t)row * ldc + col) =
                    make_float2(acc[i][j][0], acc[i][j][1]);
                *(float2*)(Cf + (size_t)(row + 8) * ldc + col) =
                    make_float2(acc[i][j][2], acc[i][j][3]);
            } else if (MODE == 1 || MODE == 3) {
                *(uint32_t*)(Ch + (size_t)row * ldc + col) =
                    pack2h(acc[i][j][0], acc[i][j][1]);
                *(uint32_t*)(Ch + (size_t)(row + 8) * ldc + col) =
                    pack2h(acc[i][j][2], acc[i][j][3]);
            } else {
                uint32_t h0, l0, h1, l1;
                splith2(acc[i][j][0] * qm0, acc[i][j][1] * qm1, h0, l0);
                splith2(acc[i][j][2] * qm0, acc[i][j][3] * qm1, h1, l1);
                *(uint32_t*)(Ch + (size_t)row * ldc + col) = h0;
                *(uint32_t*)(Cl + (size_t)row * ldc + col) = l0;
                *(uint32_t*)(Ch + (size_t)(row + 8) * ldc + col) = h1;
                *(uint32_t*)(Cl + (size_t)(row + 8) * ldc + col) = l1;
            }
        }
    }
}

// ============ fp16 2-pass causal flash attention, double-buffered K/V =======
// 64x64 tiles, 128 thr / 4 warps, warp = 16 Q rows. Tiles 64 rows x 256B.
#define AQH 0
#define AQL 16384
#define AKV 32768      /* K at AKV + b*32768, V at +16384 */
#define A_SMEM 98304

__global__ void __launch_bounds__(128) attn16() {
    extern __shared__ char asm_[];
    const uint32_t sb = smem_u32(asm_);
    const int tid = threadIdx.x;
    const int wid = tid >> 5, lane = tid & 31;
    const int qt = 31 - blockIdx.x;          // longest work first
    const int bh = blockIdx.y;
    const int b = bh >> 4, h = bh & 15;
    const size_t base = (size_t)b * SEQ * DI + (size_t)h * HD;
    const __half *qhp = g_qh + base, *qlp = g_ql + base;
    const __half *kp = g_k16 + base, *vp = g_v16 + base;

    // Q hi/lo + (K,V) tile 0 in one group
    #pragma unroll
    for (int it = 0; it < 8; ++it) {
        const int i = tid + it * 128;
        const int r = i >> 4, c = i & 15;
        const uint32_t s = (r << 8) + ((c ^ (r & 7)) << 4);
        const size_t gq = (size_t)(qt * 64 + r) * DI + c * 8;   // Q tile rows
        const size_t g0 = (size_t)r * DI + c * 8;               // K/V tile 0 rows
        cp16(sb + AQH + s, qhp + gq);
        cp16(sb + AQL + s, qlp + gq);
        cp16(sb + AKV + s, kp + g0);
        cp16(sb + AKV + 16384 + s, vp + g0);
    }
    CP_COMMIT();

    float oAcc[16][4];
    #pragma unroll
    for (int i = 0; i < 16; i++)
        #pragma unroll
        for (int j = 0; j < 4; j++) oAcc[i][j] = 0.f;
    float m0 = -1e30f, m1 = -1e30f, l0 = 0.f, l1 = 0.f;

    for (int kt = 0; kt <= qt; ++kt) {
        CP_WAIT(0);
        __syncthreads();
        if (kt < qt) {   // prefetch next K/V into other buffer
            const uint32_t dst = sb + AKV + ((kt + 1) & 1) * 32768;
            #pragma unroll
            for (int it = 0; it < 8; ++it) {
                const int i = tid + it * 128;
                const int r = i >> 4, c = i & 15;
                const size_t g = (size_t)((kt + 1) * 64 + r) * DI + c * 8;
                const uint32_t s = (r << 8) + ((c ^ (r & 7)) << 4);
                cp16(dst + s, kp + g);
                cp16(dst + 16384 + s, vp + g);
            }
            CP_COMMIT();
        }
        const uint32_t KB = sb + AKV + (kt & 1) * 32768;
        const uint32_t VB = KB + 16384;

        // ---- S = Q K^T (2-pass: q hi/lo, k single) ----
        float sAcc[8][4];
        #pragma unroll
        for (int i = 0; i < 8; i++)
            #pragma unroll
            for (int j = 0; j < 4; j++) sAcc[i][j] = 0.f;

        #pragma unroll
        for (int kk = 0; kk < 8; ++kk) {
            const int arow = wid * 16 + (lane & 15);
            const int achk = 2 * kk + (lane >> 4);
            const uint32_t aoff = (arow << 8) + ((achk ^ (arow & 7)) << 4);
            uint32_t qh[4], ql[4];
            LDSM_X4(qh, sb + AQH + aoff);
            LDSM_X4(ql, sb + AQL + aoff);
            const int brow_ = (lane & 7) + ((lane >> 4) & 1) * 8;
            const int bchk = 2 * kk + ((lane >> 3) & 1);
            #pragma unroll
            for (int g = 0; g < 4; ++g) {
                const int brow = g * 16 + brow_;
                const uint32_t boff = (brow << 8) + ((bchk ^ (brow & 7)) << 4);
                uint32_t kh[4];
                LDSM_X4(kh, KB + boff);
                MMA16816H(sAcc[2 * g],     qh, kh[0], kh[1]);
                MMA16816H(sAcc[2 * g + 1], qh, kh[2], kh[3]);
                MMA16816H(sAcc[2 * g],     ql, kh[0], kh[1]);
                MMA16816H(sAcc[2 * g + 1], ql, kh[2], kh[3]);
            }
        }

        if (kt == qt) {   // causal mask on diagonal tile
            const int colb = (lane & 3) * 2;
            const int rowa = wid * 16 + (lane >> 2);
            #pragma unroll
            for (int jt = 0; jt < 8; ++jt) {
                const int c0 = jt * 8 + colb;
                if (c0 > rowa)     sAcc[jt][0] = -1e30f;
                if (c0 + 1 > rowa) sAcc[jt][1] = -1e30f;
                if (c0 > rowa + 8)     sAcc[jt][2] = -1e30f;
                if (c0 + 1 > rowa + 8) sAcc[jt][3] = -1e30f;
            }
        }

        // ---- online softmax ----
        float mx0 = -1e30f, mx1 = -1e30f;
        #pragma unroll
        for (int jt = 0; jt < 8; ++jt) {
            mx0 = fmaxf(mx0, fmaxf(sAcc[jt][0], sAcc[jt][1]));
            mx1 = fmaxf(mx1, fmaxf(sAcc[jt][2], sAcc[jt][3]));
        }
        mx0 = fmaxf(mx0, __shfl_xor_sync(0xffffffffu, mx0, 1));
        mx0 = fmaxf(mx0, __shfl_xor_sync(0xffffffffu, mx0, 2));
        mx1 = fmaxf(mx1, __shfl_xor_sync(0xffffffffu, mx1, 1));
        mx1 = fmaxf(mx1, __shfl_xor_sync(0xffffffffu, mx1, 2));
        const float mn0 = fmaxf(m0, mx0), mn1 = fmaxf(m1, mx1);
        const float scl0 = __expf(m0 - mn0), scl1 = __expf(m1 - mn1);
        m0 = mn0; m1 = mn1;

        uint32_t ph[8][2], pl[8][2];
        float rs0 = 0.f, rs1 = 0.f;
        #pragma unroll
        for (int jt = 0; jt < 8; ++jt) {
            const float p0 = __expf(sAcc[jt][0] - mn0);
            const float p1 = __expf(sAcc[jt][1] - mn0);
            const float p2 = __expf(sAcc[jt][2] - mn1);
            const float p3 = __expf(sAcc[jt][3] - mn1);
            rs0 += p0 + p1;
            rs1 += p2 + p3;
            splith2(p0, p1, ph[jt][0], pl[jt][0]);
            splith2(p2, p3, ph[jt][1], pl[jt][1]);
        }
        rs0 += __shfl_xor_sync(0xffffffffu, rs0, 1);
        rs0 += __shfl_xor_sync(0xffffffffu, rs0, 2);
        rs1 += __shfl_xor_sync(0xffffffffu, rs1, 1);
        rs1 += __shfl_xor_sync(0xffffffffu, rs1, 2);
        l0 = l0 * scl0 + rs0;
        l1 = l1 * scl1 + rs1;
        #pragma unroll
        for (int dt = 0; dt < 16; ++dt) {
            oAcc[dt][0] *= scl0; oAcc[dt][1] *= scl0;
            oAcc[dt][2] *= scl1; oAcc[dt][3] *= scl1;
        }

        // ---- O += P V (2-pass: P hi/lo, V single via ldmatrix.trans) ----
        #pragma unroll
        for (int t = 0; t < 4; ++t) {
            uint32_t pa[4] = {ph[2 * t][0], ph[2 * t][1], ph[2 * t + 1][0], ph[2 * t + 1][1]};
            uint32_t pb[4] = {pl[2 * t][0], pl[2 * t][1], pl[2 * t + 1][0], pl[2 * t + 1][1]};
            const int vrow = t * 16 + (lane & 7) + ((lane >> 3) & 1) * 8;
            #pragma unroll
            for (int g = 0; g < 8; ++g) {
                const int vchk = 2 * g + (lane >> 4);
                const uint32_t voff = (vrow << 8) + ((vchk ^ (vrow & 7)) << 4);
                uint32_t vh[4];
                LDSM_X4_T(vh, VB + voff);
                MMA16816H(oAcc[2 * g],     pa, vh[0], vh[1]);
                MMA16816H(oAcc[2 * g + 1], pa, vh[2], vh[3]);
                MMA16816H(oAcc[2 * g],     pb, vh[0], vh[1]);
                MMA16816H(oAcc[2 * g + 1], pb, vh[2], vh[3]);
            }
        }
    }

    // ---- epilogue: /l, fold Wout col-norm, emit fp16 hi/lo ----
    const float li0 = 1.f / l0, li1 = 1.f / l1;
    const int row0 = qt * 64 + wid * 16 + (lane >> 2);
    const int colb = (lane & 3) * 2;
    __half* ohp = g_oh + base;
    __half* olp = g_ol + base;
    #pragma unroll
    for (int dt = 0; dt < 16; ++dt) {
        const int d = dt * 8 + colb;
        const float2 ro = *(const float2*)&g_rinv[3][h * HD + d];
        const float v0 = oAcc[dt][0] * li0 * ro.x;
        const float v1 = oAcc[dt][1] * li0 * ro.y;
        const float v2 = oAcc[dt][2] * li1 * ro.x;
        const float v3 = oAcc[dt][3] * li1 * ro.y;
        uint32_t h0, lo0, h1, lo1;
        splith2(v0, v1, h0, lo0);
        splith2(v2, v3, h1, lo1);
        const size_t o0 = (size_t)row0 * DI + d;
        const size_t o1 = (size_t)(row0 + 8) * DI + d;
        *(uint32_t*)(ohp + o0) = h0;
        *(uint32_t*)(olp + o0) = lo0;
        *(uint32_t*)(ohp + o1) = h1;
        *(uint32_t*)(olp + o1) = lo1;
    }
}

// ============================== host side ====================================
extern "C" void kernel_launch(void* const* d_in, const int* in_sizes, int n_in,
                              void* d_out, int out_size) {
    (void)in_sizes; (void)n_in; (void)out_size;
    const float* x    = (const float*)d_in[0];
    const float* Wq   = (const float*)d_in[1];
    const float* Wk   = (const float*)d_in[2];
    const float* Wv   = (const float*)d_in[3];
    const float* Wout = (const float*)d_in[4];
    const float* qk   = (const float*)d_in[5];
    float* out = (float*)d_out;

    float* pr;
    __half *pxh, *pxl, *pw, *pqh, *pql, *pk16, *pv16, *poh, *pol;
    cudaGetSymbolAddress((void**)&pr, g_rinv);
    cudaGetSymbolAddress((void**)&pxh, g_xh);
    cudaGetSymbolAddress((void**)&pxl, g_xl);
    cudaGetSymbolAddress((void**)&pw, g_w16);
    cudaGetSymbolAddress((void**)&pqh, g_qh);
    cudaGetSymbolAddress((void**)&pql, g_ql);
    cudaGetSymbolAddress((void**)&pk16, g_k16);
    cudaGetSymbolAddress((void**)&pv16, g_v16);
    cudaGetSymbolAddress((void**)&poh, g_oh);
    cudaGetSymbolAddress((void**)&pol, g_ol);

    const size_t WSZ = (size_t)DIM * DIM;
    const int gsmem = 3 * GS_STAGE;   // 72KB
    cudaFuncSetAttribute(gemm16<0>, cudaFuncAttributeMaxDynamicSharedMemorySize, gsmem);
    cudaFuncSetAttribute(gemm16<1>, cudaFuncAttributeMaxDynamicSharedMemorySize, gsmem);
    cudaFuncSetAttribute(gemm16<2>, cudaFuncAttributeMaxDynamicSharedMemorySize, gsmem);
    cudaFuncSetAttribute(gemm16<3>, cudaFuncAttributeMaxDynamicSharedMemorySize, gsmem);
    cudaFuncSetAttribute(attn16, cudaFuncAttributeMaxDynamicSharedMemorySize, A_SMEM);

    // converts + norms
    convert_x16<<<(MTOT * DIM / 4) / 256, 256>>>(
        (const float4*)x, (uint32_t*)pxh, (uint32_t*)pxl);
    convert_w16<<<DIM, 256>>>(Wq, pw + 0 * WSZ, 0);
    convert_w16<<<DIM, 256>>>(Wk, pw + 1 * WSZ, 1);
    convert_w16<<<DIM, 256>>>(Wv, pw + 2 * WSZ, 2);
    convert_flat16<<<(DIM * DIM / 4) / 256, 256>>>(
        (const float4*)Wout, (uint32_t*)(pw + 3 * WSZ));
    colnorm_part<<<dim3(DIM / 256, 16), 256>>>(Wout);
    colnorm_fin<<<DIM / 256, 256>>>();

    // QKV projections with fused epilogues
    dim3 gg(DI / 128, MTOT / 128);   // (16, 32)
    gemm16<2><<<gg, 256, gsmem>>>(pxh, pxl, pw + 0 * WSZ, nullptr, pqh, pql,
                                  pr + 0 * DIM, qk, DI);
    gemm16<3><<<gg, 256, gsmem>>>(pxh, pxl, pw + 1 * WSZ, nullptr, pk16, nullptr,
                                  pr + 1 * DIM, nullptr, DI);
    gemm16<1><<<gg, 256, gsmem>>>(pxh, pxl, pw + 2 * WSZ, nullptr, pv16, nullptr,
                                  pr + 2 * DIM, nullptr, DI);

    // attention (emits o fp16 hi/lo, Wout col-norm folded)
    attn16<<<dim3(SEQ / 64, BATCH * HEADS), 128, A_SMEM>>>();

    // output projection
    gemm16<0><<<dim3(DIM / 128, MTOT / 128), 256, gsmem>>>(
        poh, pol, pw + 3 * WSZ, out, nullptr, nullptr, nullptr, nullptr, DIM);
}

// round 7
// speedup vs baseline: 5.7703x; 1.6164x over previous
#include <cuda_runtime.h>
#include <cuda_fp16.h>
#include <math.h>
#include <stdint.h>

#define BATCH 2
#define SEQ 2048
#define DIM 2048
#define HEADS 16
#define HD 128
#define DI 2048           /* HEADS*HD */
#define MTOT (BATCH*SEQ)  /* 4096 */

// ---------------- scratch (device globals: allocation-free rule) ------------
__device__ float g_rinv[4][DIM];     // 0:Wq rows 1:Wk rows 2:Wv rows 3:Wout cols
__device__ float g_colpart[16][DIM];
__device__ __half g_x16[(size_t)MTOT * DIM];
__device__ __half g_w16[4][(size_t)DIM * DIM];   // q,k,v,out
__device__ __half g_q16[(size_t)MTOT * DI];
__device__ __half g_k16[(size_t)MTOT * DI];
__device__ __half g_v16[(size_t)MTOT * DI];
__device__ __half g_o16[(size_t)MTOT * DI];

// ============================ PTX helpers (sm_80+ portable) =================
__device__ __forceinline__ uint32_t smem_u32(const void* p) {
    uint32_t a;
    asm("{ .reg .u64 t; cvta.to.shared.u64 t, %1; cvt.u32.u64 %0, t; }"
        : "=r"(a) : "l"(p));
    return a;
}

__device__ __forceinline__ void cp16(uint32_t saddr, const void* g) {
    asm volatile("cp.async.cg.shared.global [%0], [%1], 16;"
                 :: "r"(saddr), "l"(g) : "memory");
}
#define CP_COMMIT() asm volatile("cp.async.commit_group;" ::: "memory")
#define CP_WAIT(n)  asm volatile("cp.async.wait_group %0;" :: "n"(n) : "memory")

#define LDSM_X4(r, addr) \
    asm volatile("ldmatrix.sync.aligned.m8n8.x4.shared.b16 {%0,%1,%2,%3}, [%4];" \
        : "=r"((r)[0]), "=r"((r)[1]), "=r"((r)[2]), "=r"((r)[3]) : "r"(addr))

#define LDSM_X4_T(r, addr) \
    asm volatile("ldmatrix.sync.aligned.m8n8.x4.trans.shared.b16 {%0,%1,%2,%3}, [%4];" \
        : "=r"((r)[0]), "=r"((r)[1]), "=r"((r)[2]), "=r"((r)[3]) : "r"(addr))

#define MMA16816H(d, a, b0, b1) \
    asm volatile("mma.sync.aligned.m16n8k16.row.col.f32.f16.f16.f32 " \
        "{%0,%1,%2,%3}, {%4,%5,%6,%7}, {%8,%9}, {%0,%1,%2,%3};" \
        : "+f"((d)[0]), "+f"((d)[1]), "+f"((d)[2]), "+f"((d)[3]) \
        : "r"((a)[0]), "r"((a)[1]), "r"((a)[2]), "r"((a)[3]), "r"(b0), "r"(b1))

__device__ __forceinline__ uint32_t pack2h(float a, float b) {
    uint32_t r;
    asm("cvt.rn.f16x2.f32 %0, %1, %2;" : "=r"(r) : "f"(b), "f"(a));
    return r;
}

// ================= fp32 -> fp16 converters (+ fused norms) ==================
__global__ void convert_flat16(const float4* __restrict__ W, uint32_t* __restrict__ o) {
    int i = blockIdx.x * 256 + threadIdx.x;
    float4 v = W[i];
    o[2 * i] = pack2h(v.x, v.y);
    o[2 * i + 1] = pack2h(v.z, v.w);
}

// fused q/k/v weight convert: one block per (row, which); + row l2 norm recip
__global__ void convert_wqkv16(const float* __restrict__ Wq,
                               const float* __restrict__ Wk,
                               const float* __restrict__ Wv,
                               __half* __restrict__ o) {
    __shared__ float red[8];
    const int row = blockIdx.x, sel = blockIdx.y, tid = threadIdx.x;
    const float* W = sel == 0 ? Wq : (sel == 1 ? Wk : Wv);
    const float4* p = (const float4*)(W + (size_t)row * DIM);
    uint32_t* op = (uint32_t*)(o + (size_t)sel * DIM * DIM + (size_t)row * DIM);
    float s = 0.f;
    #pragma unroll
    for (int i = tid; i < DIM / 4; i += 256) {
        float4 v = p[i];
        s += v.x * v.x + v.y * v.y + v.z * v.z + v.w * v.w;
        op[2 * i] = pack2h(v.x, v.y);
        op[2 * i + 1] = pack2h(v.z, v.w);
    }
    #pragma unroll
    for (int off = 16; off; off >>= 1) s += __shfl_xor_sync(0xffffffffu, s, off);
    if ((tid & 31) == 0) red[tid >> 5] = s;
    __syncthreads();
    if (tid == 0) {
        float t = 0.f;
        #pragma unroll
        for (int i = 0; i < 8; i++) t += red[i];
        g_rinv[sel][row] = 1.f / fmaxf(sqrtf(t), 1e-12f);
    }
}

// Wout column-norm: two-phase deterministic parallel reduce
__global__ void colnorm_part(const float* __restrict__ W) {
    const int col = blockIdx.x * 256 + threadIdx.x;
    const int r0 = blockIdx.y * 128;
    float s = 0.f;
    for (int r = 0; r < 128; ++r) {
        float v = W[(size_t)(r0 + r) * DI + col];
        s += v * v;
    }
    g_colpart[blockIdx.y][col] = s;
}
__global__ void colnorm_fin() {
    int c = blockIdx.x * 256 + threadIdx.x;
    float s = 0.f;
    #pragma unroll
    for (int i = 0; i < 16; ++i) s += g_colpart[i][c];
    g_rinv[3][c] = 1.f / fmaxf(sqrtf(s), 1e-12f);
}

// =================== fp16 single-pass NT GEMM ================================
// C[m,n] = sum_k A[m,k]*B[n,k]; 128x128x32 CTA tile, 3-stage cp.async.
// MODE 0: fp32 out                     MODE 1: *rinv -> fp16 out (v)
// MODE 2: *rinv, headnorm, *qks*DIM*sqrt(HD) -> fp16 out (q)
// MODE 3: *rinv, headnorm -> fp16 out (k)
#define GS_MAT 8192
#define GS_STAGE 16384
#define GS_NKT (DIM / 32)   /* 64 */

template<int MODE>
__global__ void __launch_bounds__(256) gemm16(
    const __half* __restrict__ Ag, const __half* __restrict__ Bg,
    float* __restrict__ Cf, __half* __restrict__ Ch,
    const float* __restrict__ rinv, const float* __restrict__ qks, int ldc)
{
    extern __shared__ char smem[];
    const uint32_t sb = smem_u32(smem);
    const int tid = threadIdx.x;
    const int wid = tid >> 5, lane = tid & 31;
    const int wm = wid & 3, wn = wid >> 2;
    const int mbase = blockIdx.y * 128, nbase = blockIdx.x * 128;

    auto load_stage = [&](int kt, int buf) {
        const uint32_t st = sb + buf * GS_STAGE;
        const int koff = kt * 32;
        #pragma unroll
        for (int h = 0; h < 2; ++h) {
            const int cid = tid + h * 256;
            const int r = cid >> 2, c = cid & 3;
            const uint32_t aoff = ((c >> 1) << 12) + ((r >> 4) << 9) +
                (((r & 7) + ((r >> 3) & 1) * 8 + (c & 1) * 16) << 4);
            const uint32_t boff = ((c >> 1) << 12) + ((r >> 4) << 9) +
                (((r & 7) + (c & 1) * 8 + ((r >> 3) & 1) * 16) << 4);
            cp16(st + aoff, Ag + (size_t)(mbase + r) * DIM + koff + c * 8);
            cp16(st + GS_MAT + boff, Bg + (size_t)(nbase + r) * DIM + koff + c * 8);
        }
    };

    float acc[2][8][4];
    #pragma unroll
    for (int i = 0; i < 2; i++)
        #pragma unroll
        for (int j = 0; j < 8; j++)
            #pragma unroll
            for (int t = 0; t < 4; t++) acc[i][j][t] = 0.f;

    load_stage(0, 0); CP_COMMIT();
    load_stage(1, 1); CP_COMMIT();

    for (int kt = 0; kt < GS_NKT; ++kt) {
        CP_WAIT(1);          // oldest real group (kt) complete
        __syncthreads();     // data visible; compute(kt-1) done
        if (kt + 2 < GS_NKT) load_stage(kt + 2, (kt + 2) % 3);
        CP_COMMIT();         // always commit (empty ok) to keep wait semantics
        const uint32_t stg = sb + (kt % 3) * GS_STAGE;
        #pragma unroll
        for (int s = 0; s < 2; ++s) {
            const uint32_t aA = stg + (s << 12) + ((wm * 2) << 9) + lane * 16;
            const uint32_t bA = stg + GS_MAT + (s << 12) + ((wn * 4) << 9) + lane * 16;
            uint32_t a0[4], a1[4], b[4][4];
            LDSM_X4(a0, aA);
            LDSM_X4(a1, aA + 512);
            #pragma unroll
            for (int jt = 0; jt < 4; ++jt) LDSM_X4(b[jt], bA + jt * 512);
            #pragma unroll
            for (int jt = 0; jt < 4; ++jt) {
                MMA16816H(acc[0][2 * jt],     a0, b[jt][0], b[jt][1]);
                MMA16816H(acc[0][2 * jt + 1], a0, b[jt][2], b[jt][3]);
                MMA16816H(acc[1][2 * jt],     a1, b[jt][0], b[jt][1]);
                MMA16816H(acc[1][2 * jt + 1], a1, b[jt][2], b[jt][3]);
            }
        }
    }
    __syncthreads();

    // -------- epilogue --------
    const int lr0 = wm * 32 + (lane >> 2);
    if (rinv) {
        #pragma unroll
        for (int j = 0; j < 8; ++j) {
            const int col = nbase + wn * 64 + j * 8 + (lane & 3) * 2;
            const float s0 = rinv[col], s1 = rinv[col + 1];
            #pragma unroll
            for (int i = 0; i < 2; ++i) {
                acc[i][j][0] *= s0; acc[i][j][1] *= s1;
                acc[i][j][2] *= s0; acc[i][j][3] *= s1;
            }
        }
    }
    if (MODE == 2 || MODE == 3) {
        // per-row l2 norm over this CTA's 128 cols (= one head)
        float ssq[4] = {0.f, 0.f, 0.f, 0.f};
        #pragma unroll
        for (int i = 0; i < 2; ++i)
            #pragma unroll
            for (int j = 0; j < 8; ++j) {
                ssq[2 * i]     += acc[i][j][0] * acc[i][j][0] + acc[i][j][1] * acc[i][j][1];
                ssq[2 * i + 1] += acc[i][j][2] * acc[i][j][2] + acc[i][j][3] * acc[i][j][3];
            }
        #pragma unroll
        for (int r = 0; r < 4; ++r) {
            ssq[r] += __shfl_xor_sync(0xffffffffu, ssq[r], 1);
            ssq[r] += __shfl_xor_sync(0xffffffffu, ssq[r], 2);
        }
        float* red = (float*)smem;   // reuse pipeline smem: [2][128]
        if ((lane & 3) == 0) {
            #pragma unroll
            for (int r = 0; r < 4; ++r)
                red[wn * 128 + lr0 + (r & 1) * 8 + (r >> 1) * 16] = ssq[r];
        }
        __syncthreads();
        float rn_[4];
        #pragma unroll
        for (int r = 0; r < 4; ++r) {
            const int lr = lr0 + (r & 1) * 8 + (r >> 1) * 16;
            rn_[r] = 1.f / fmaxf(sqrtf(red[lr] + red[128 + lr]), 1e-12f);
        }
        #pragma unroll
        for (int i = 0; i < 2; ++i)
            #pragma unroll
            for (int j = 0; j < 8; ++j) {
                acc[i][j][0] *= rn_[2 * i];     acc[i][j][1] *= rn_[2 * i];
                acc[i][j][2] *= rn_[2 * i + 1]; acc[i][j][3] *= rn_[2 * i + 1];
            }
    }
    #pragma unroll
    for (int j = 0; j < 8; ++j) {
        const int col = nbase + wn * 64 + j * 8 + (lane & 3) * 2;
        float qm0 = 1.f, qm1 = 1.f;
        if (MODE == 2) {
            qm0 = qks[col] * 23170.475005920826f;      // DIM * sqrt(HD)
            qm1 = qks[col + 1] * 23170.475005920826f;
        }
        #pragma unroll
        for (int i = 0; i < 2; ++i) {
            const int row = mbase + lr0 + i * 16;
            if (MODE == 0) {
                *(float2*)(Cf + (size_t)row * ldc + col) =
                    make_float2(acc[i][j][0], acc[i][j][1]);
                *(float2*)(Cf + (size_t)(row + 8) * ldc + col) =
                    make_float2(acc[i][j][2], acc[i][j][3]);
            } else {
                *(uint32_t*)(Ch + (size_t)row * ldc + col) =
                    pack2h(acc[i][j][0] * qm0, acc[i][j][1] * qm1);
                *(uint32_t*)(Ch + (size_t)(row + 8) * ldc + col) =
                    pack2h(acc[i][j][2] * qm0, acc[i][j][3] * qm1);
            }
        }
    }
}

// ============ fp16 single-pass causal flash attention, dbl-buffered K/V =====
// 64x64 tiles, 128 thr / 4 warps, warp = 16 Q rows. Tiles 64 rows x 256B.
#define AQ 0
#define AKV 16384      /* buffer b at AKV + b*32768: K 16KB then V 16KB */
#define A_SMEM 81920

__global__ void __launch_bounds__(128) attn16() {
    extern __shared__ char asm_[];
    const uint32_t sb = smem_u32(asm_);
    const int tid = threadIdx.x;
    const int wid = tid >> 5, lane = tid & 31;
    const int qt = 31 - blockIdx.x;          // longest work first
    const int bh = blockIdx.y;
    const int b = bh >> 4, h = bh & 15;
    const size_t base = (size_t)b * SEQ * DI + (size_t)h * HD;
    const __half *qp = g_q16 + base;
    const __half *kp = g_k16 + base, *vp = g_v16 + base;

    // Q + (K,V) tile 0 in one group
    #pragma unroll
    for (int it = 0; it < 8; ++it) {
        const int i = tid + it * 128;
        const int r = i >> 4, c = i & 15;
        const uint32_t s = (r << 8) + ((c ^ (r & 7)) << 4);
        cp16(sb + AQ + s, qp + (size_t)(qt * 64 + r) * DI + c * 8);
        const size_t g0 = (size_t)r * DI + c * 8;    // K/V tile 0 rows
        cp16(sb + AKV + s, kp + g0);
        cp16(sb + AKV + 16384 + s, vp + g0);
    }
    CP_COMMIT();

    float oAcc[16][4];
    #pragma unroll
    for (int i = 0; i < 16; i++)
        #pragma unroll
        for (int j = 0; j < 4; j++) oAcc[i][j] = 0.f;
    float m0 = -1e30f, m1 = -1e30f, l0 = 0.f, l1 = 0.f;

    for (int kt = 0; kt <= qt; ++kt) {
        CP_WAIT(0);
        __syncthreads();
        if (kt < qt) {   // prefetch next K/V into other buffer
            const uint32_t dst = sb + AKV + ((kt + 1) & 1) * 32768;
            #pragma unroll
            for (int it = 0; it < 8; ++it) {
                const int i = tid + it * 128;
                const int r = i >> 4, c = i & 15;
                const size_t g = (size_t)((kt + 1) * 64 + r) * DI + c * 8;
                const uint32_t s = (r << 8) + ((c ^ (r & 7)) << 4);
                cp16(dst + s, kp + g);
                cp16(dst + 16384 + s, vp + g);
            }
            CP_COMMIT();
        }
        const uint32_t KB = sb + AKV + (kt & 1) * 32768;
        const uint32_t VB = KB + 16384;

        // ---- S = Q K^T ----
        float sAcc[8][4];
        #pragma unroll
        for (int i = 0; i < 8; i++)
            #pragma unroll
            for (int j = 0; j < 4; j++) sAcc[i][j] = 0.f;

        #pragma unroll
        for (int kk = 0; kk < 8; ++kk) {
            const int arow = wid * 16 + (lane & 15);
            const int achk = 2 * kk + (lane >> 4);
            const uint32_t aoff = (arow << 8) + ((achk ^ (arow & 7)) << 4);
            uint32_t qf[4];
            LDSM_X4(qf, sb + AQ + aoff);
            const int brow_ = (lane & 7) + ((lane >> 4) & 1) * 8;
            const int bchk = 2 * kk + ((lane >> 3) & 1);
            #pragma unroll
            for (int g = 0; g < 4; ++g) {
                const int brow = g * 16 + brow_;
                const uint32_t boff = (brow << 8) + ((bchk ^ (brow & 7)) << 4);
                uint32_t kf[4];
                LDSM_X4(kf, KB + boff);
                MMA16816H(sAcc[2 * g],     qf, kf[0], kf[1]);
                MMA16816H(sAcc[2 * g + 1], qf, kf[2], kf[3]);
            }
        }

        if (kt == qt) {   // causal mask on diagonal tile
            const int colb = (lane & 3) * 2;
            const int rowa = wid * 16 + (lane >> 2);
            #pragma unroll
            for (int jt = 0; jt < 8; ++jt) {
                const int c0 = jt * 8 + colb;
                if (c0 > rowa)     sAcc[jt][0] = -1e30f;
                if (c0 + 1 > rowa) sAcc[jt][1] = -1e30f;
                if (c0 > rowa + 8)     sAcc[jt][2] = -1e30f;
                if (c0 + 1 > rowa + 8) sAcc[jt][3] = -1e30f;
            }
        }

        // ---- online softmax ----
        float mx0 = -1e30f, mx1 = -1e30f;
        #pragma unroll
        for (int jt = 0; jt < 8; ++jt) {
            mx0 = fmaxf(mx0, fmaxf(sAcc[jt][0], sAcc[jt][1]));
            mx1 = fmaxf(mx1, fmaxf(sAcc[jt][2], sAcc[jt][3]));
        }
        mx0 = fmaxf(mx0, __shfl_xor_sync(0xffffffffu, mx0, 1));
        mx0 = fmaxf(mx0, __shfl_xor_sync(0xffffffffu, mx0, 2));
        mx1 = fmaxf(mx1, __shfl_xor_sync(0xffffffffu, mx1, 1));
        mx1 = fmaxf(mx1, __shfl_xor_sync(0xffffffffu, mx1, 2));
        const float mn0 = fmaxf(m0, mx0), mn1 = fmaxf(m1, mx1);
        const float scl0 = __expf(m0 - mn0), scl1 = __expf(m1 - mn1);
        m0 = mn0; m1 = mn1;

        uint32_t ph[8][2];
        float rs0 = 0.f, rs1 = 0.f;
        #pragma unroll
        for (int jt = 0; jt < 8; ++jt) {
            const float p0 = __expf(sAcc[jt][0] - mn0);
            const float p1 = __expf(sAcc[jt][1] - mn0);
            const float p2 = __expf(sAcc[jt][2] - mn1);
            const float p3 = __expf(sAcc[jt][3] - mn1);
            rs0 += p0 + p1;
            rs1 += p2 + p3;
            ph[jt][0] = pack2h(p0, p1);
            ph[jt][1] = pack2h(p2, p3);
        }
        rs0 += __shfl_xor_sync(0xffffffffu, rs0, 1);
        rs0 += __shfl_xor_sync(0xffffffffu, rs0, 2);
        rs1 += __shfl_xor_sync(0xffffffffu, rs1, 1);
        rs1 += __shfl_xor_sync(0xffffffffu, rs1, 2);
        l0 = l0 * scl0 + rs0;
        l1 = l1 * scl1 + rs1;
        #pragma unroll
        for (int dt = 0; dt < 16; ++dt) {
            oAcc[dt][0] *= scl0; oAcc[dt][1] *= scl0;
            oAcc[dt][2] *= scl1; oAcc[dt][3] *= scl1;
        }

        // ---- O += P V (V via ldmatrix.trans) ----
        #pragma unroll
        for (int t = 0; t < 4; ++t) {
            uint32_t pa[4] = {ph[2 * t][0], ph[2 * t][1], ph[2 * t + 1][0], ph[2 * t + 1][1]};
            const int vrow = t * 16 + (lane & 7) + ((lane >> 3) & 1) * 8;
            #pragma unroll
            for (int g = 0; g < 8; ++g) {
                const int vchk = 2 * g + (lane >> 4);
                const uint32_t voff = (vrow << 8) + ((vchk ^ (vrow & 7)) << 4);
                uint32_t vf[4];
                LDSM_X4_T(vf, VB + voff);
                MMA16816H(oAcc[2 * g],     pa, vf[0], vf[1]);
                MMA16816H(oAcc[2 * g + 1], pa, vf[2], vf[3]);
            }
        }
    }

    // ---- epilogue: /l, fold Wout col-norm, emit fp16 ----
    const float li0 = 1.f / l0, li1 = 1.f / l1;
    const int row0 = qt * 64 + wid * 16 + (lane >> 2);
    const int colb = (lane & 3) * 2;
    __half* op = g_o16 + base;
    #pragma unroll
    for (int dt = 0; dt < 16; ++dt) {
        const int d = dt * 8 + colb;
        const float2 ro = *(const float2*)&g_rinv[3][h * HD + d];
        *(uint32_t*)(op + (size_t)row0 * DI + d) =
            pack2h(oAcc[dt][0] * li0 * ro.x, oAcc[dt][1] * li0 * ro.y);
        *(uint32_t*)(op + (size_t)(row0 + 8) * DI + d) =
            pack2h(oAcc[dt][2] * li1 * ro.x, oAcc[dt][3] * li1 * ro.y);
    }
}

// ============================== host side ====================================
extern "C" void kernel_launch(void* const* d_in, const int* in_sizes, int n_in,
                              void* d_out, int out_size) {
    (void)in_sizes; (void)n_in; (void)out_size;
    const float* x    = (const float*)d_in[0];
    const float* Wq   = (const float*)d_in[1];
    const float* Wk   = (const float*)d_in[2];
    const float* Wv   = (const float*)d_in[3];
    const float* Wout = (const float*)d_in[4];
    const float* qk   = (const float*)d_in[5];
    float* out = (float*)d_out;

    float* pr;
    __half *px, *pw, *pq, *pk16, *pv16, *po;
    cudaGetSymbolAddress((void**)&pr, g_rinv);
    cudaGetSymbolAddress((void**)&px, g_x16);
    cudaGetSymbolAddress((void**)&pw, g_w16);
    cudaGetSymbolAddress((void**)&pq, g_q16);
    cudaGetSymbolAddress((void**)&pk16, g_k16);
    cudaGetSymbolAddress((void**)&pv16, g_v16);
    cudaGetSymbolAddress((void**)&po, g_o16);

    const size_t WSZ = (size_t)DIM * DIM;
    const int gsmem = 3 * GS_STAGE;   // 48KB
    cudaFuncSetAttribute(gemm16<0>, cudaFuncAttributeMaxDynamicSharedMemorySize, gsmem);
    cudaFuncSetAttribute(gemm16<1>, cudaFuncAttributeMaxDynamicSharedMemorySize, gsmem);
    cudaFuncSetAttribute(gemm16<2>, cudaFuncAttributeMaxDynamicSharedMemorySize, gsmem);
    cudaFuncSetAttribute(gemm16<3>, cudaFuncAttributeMaxDynamicSharedMemorySize, gsmem);
    cudaFuncSetAttribute(attn16, cudaFuncAttributeMaxDynamicSharedMemorySize, A_SMEM);

    // launches 0-4: converts + norms
    convert_flat16<<<(MTOT * DIM / 4) / 256, 256>>>((const float4*)x, (uint32_t*)px);
    convert_wqkv16<<<dim3(DIM, 3), 256>>>(Wq, Wk, Wv, pw);
    convert_flat16<<<(DIM * DIM / 4) / 256, 256>>>(
        (const float4*)Wout, (uint32_t*)(pw + 3 * WSZ));
    colnorm_part<<<dim3(DIM / 256, 16), 256>>>(Wout);
    colnorm_fin<<<DIM / 256, 256>>>();

    // launches 5-7: QKV projections (launch 5 = Q GEMM for ncu -s 5)
    dim3 gg(DI / 128, MTOT / 128);   // (16, 32)
    gemm16<2><<<gg, 256, gsmem>>>(px, pw + 0 * WSZ, nullptr, pq, pr + 0 * DIM, qk, DI);
    gemm16<3><<<gg, 256, gsmem>>>(px, pw + 1 * WSZ, nullptr, pk16, pr + 1 * DIM, nullptr, DI);
    gemm16<1><<<gg, 256, gsmem>>>(px, pw + 2 * WSZ, nullptr, pv16, pr + 2 * DIM, nullptr, DI);

    // launch 8: attention (emits o fp16, Wout col-norm folded)
    attn16<<<dim3(SEQ / 64, BATCH * HEADS), 128, A_SMEM>>>();

    // launch 9: output projection
    gemm16<0><<<dim3(DIM / 128, MTOT / 128), 256, gsmem>>>(
        po, pw + 3 * WSZ, out, nullptr, nullptr, nullptr, DIM);
}

// round 8
// speedup vs baseline: 6.2644x; 1.0856x over previous
#include <cuda_runtime.h>
#include <cuda_fp16.h>
#include <math.h>
#include <stdint.h>

#define BATCH 2
#define SEQ 2048
#define DIM 2048
#define HEADS 16
#define HD 128
#define DI 2048           /* HEADS*HD */
#define MTOT (BATCH*SEQ)  /* 4096 */

// ---------------- scratch (device globals: allocation-free rule) ------------
__device__ float g_rinv[4][DIM];     // 0:Wq rows 1:Wk rows 2:Wv rows 3:Wout cols
__device__ float g_colpart[16][DIM];
__device__ __half g_x16[(size_t)MTOT * DIM];
__device__ __half g_w16[4][(size_t)DIM * DIM];   // q,k,v,out
__device__ __half g_q16[(size_t)MTOT * DI];
__device__ __half g_k16[(size_t)MTOT * DI];
__device__ __half g_v16[(size_t)MTOT * DI];
__device__ __half g_o16[(size_t)MTOT * DI];

// ============================ PTX helpers (sm_80+ portable) =================
__device__ __forceinline__ uint32_t smem_u32(const void* p) {
    uint32_t a;
    asm("{ .reg .u64 t; cvta.to.shared.u64 t, %1; cvt.u32.u64 %0, t; }"
        : "=r"(a) : "l"(p));
    return a;
}

__device__ __forceinline__ void cp16(uint32_t saddr, const void* g) {
    asm volatile("cp.async.cg.shared.global [%0], [%1], 16;"
                 :: "r"(saddr), "l"(g) : "memory");
}
#define CP_COMMIT() asm volatile("cp.async.commit_group;" ::: "memory")
#define CP_WAIT(n)  asm volatile("cp.async.wait_group %0;" :: "n"(n) : "memory")

#define LDSM_X4(r, addr) \
    asm volatile("ldmatrix.sync.aligned.m8n8.x4.shared.b16 {%0,%1,%2,%3}, [%4];" \
        : "=r"((r)[0]), "=r"((r)[1]), "=r"((r)[2]), "=r"((r)[3]) : "r"(addr))

#define LDSM_X4_T(r, addr) \
    asm volatile("ldmatrix.sync.aligned.m8n8.x4.trans.shared.b16 {%0,%1,%2,%3}, [%4];" \
        : "=r"((r)[0]), "=r"((r)[1]), "=r"((r)[2]), "=r"((r)[3]) : "r"(addr))

#define MMA16816H(d, a, b0, b1) \
    asm volatile("mma.sync.aligned.m16n8k16.row.col.f32.f16.f16.f32 " \
        "{%0,%1,%2,%3}, {%4,%5,%6,%7}, {%8,%9}, {%0,%1,%2,%3};" \
        : "+f"((d)[0]), "+f"((d)[1]), "+f"((d)[2]), "+f"((d)[3]) \
        : "r"((a)[0]), "r"((a)[1]), "r"((a)[2]), "r"((a)[3]), "r"(b0), "r"(b1))

__device__ __forceinline__ uint32_t pack2h(float a, float b) {
    uint32_t r;
    asm("cvt.rn.f16x2.f32 %0, %1, %2;" : "=r"(r) : "f"(b), "f"(a));
    return r;
}
__device__ __forceinline__ float ex2f(float x) {
    float r;
    asm("ex2.approx.ftz.f32 %0, %1;" : "=f"(r) : "f"(x));
    return r;
}

// ================= fp32 -> fp16 converters (+ fused norms) ==================
__global__ void convert_flat16(const float4* __restrict__ W, uint32_t* __restrict__ o) {
    int i = blockIdx.x * 256 + threadIdx.x;
    float4 v = W[i];
    o[2 * i] = pack2h(v.x, v.y);
    o[2 * i + 1] = pack2h(v.z, v.w);
}

// fused q/k/v weight convert: one block per (row, which); + row l2 norm recip
__global__ void convert_wqkv16(const float* __restrict__ Wq,
                               const float* __restrict__ Wk,
                               const float* __restrict__ Wv,
                               __half* __restrict__ o) {
    __shared__ float red[8];
    const int row = blockIdx.x, sel = blockIdx.y, tid = threadIdx.x;
    const float* W = sel == 0 ? Wq : (sel == 1 ? Wk : Wv);
    const float4* p = (const float4*)(W + (size_t)row * DIM);
    uint32_t* op = (uint32_t*)(o + (size_t)sel * DIM * DIM + (size_t)row * DIM);
    float s = 0.f;
    #pragma unroll
    for (int i = tid; i < DIM / 4; i += 256) {
        float4 v = p[i];
        s += v.x * v.x + v.y * v.y + v.z * v.z + v.w * v.w;
        op[2 * i] = pack2h(v.x, v.y);
        op[2 * i + 1] = pack2h(v.z, v.w);
    }
    #pragma unroll
    for (int off = 16; off; off >>= 1) s += __shfl_xor_sync(0xffffffffu, s, off);
    if ((tid & 31) == 0) red[tid >> 5] = s;
    __syncthreads();
    if (tid == 0) {
        float t = 0.f;
        #pragma unroll
        for (int i = 0; i < 8; i++) t += red[i];
        g_rinv[sel][row] = 1.f / fmaxf(sqrtf(t), 1e-12f);
    }
}

// Wout column-norm: two-phase deterministic parallel reduce
__global__ void colnorm_part(const float* __restrict__ W) {
    const int col = blockIdx.x * 256 + threadIdx.x;
    const int r0 = blockIdx.y * 128;
    float s = 0.f;
    for (int r = 0; r < 128; ++r) {
        float v = W[(size_t)(r0 + r) * DI + col];
        s += v * v;
    }
    g_colpart[blockIdx.y][col] = s;
}
__global__ void colnorm_fin() {
    int c = blockIdx.x * 256 + threadIdx.x;
    float s = 0.f;
    #pragma unroll
    for (int i = 0; i < 16; ++i) s += g_colpart[i][c];
    g_rinv[3][c] = 1.f / fmaxf(sqrtf(s), 1e-12f);
}

// =================== fp16 single-pass NT GEMM, 128x128x64 tiles ==============
// Shared mainloop: 3-stage cp.async, k-tile 64, one sync per k-tile.
#define GS_MAT 16384
#define GS_STAGE 32768
#define GS_NKT (DIM / 64)   /* 32 */

struct GAcc { float a[2][8][4]; };

__device__ __forceinline__ void gemm_mainloop(
    const __half* __restrict__ Ag, const __half* __restrict__ Bg,
    uint32_t sb, int tid, int mbase, int nbase, GAcc& acc)
{
    const int wid = tid >> 5, lane = tid & 31;
    const int wm = wid & 3, wn = wid >> 2;

    auto load_stage = [&](int kt, int buf) {
        const uint32_t st = sb + buf * GS_STAGE;
        const int koff = kt * 64;
        #pragma unroll
        for (int h = 0; h < 4; ++h) {
            const int cid = tid + h * 256;
            const int r = cid >> 3, c = cid & 7;
            const uint32_t aoff = ((c >> 1) << 12) + ((r >> 4) << 9) +
                (((r & 7) + ((r >> 3) & 1) * 8 + (c & 1) * 16) << 4);
            const uint32_t boff = ((c >> 1) << 12) + ((r >> 4) << 9) +
                (((r & 7) + (c & 1) * 8 + ((r >> 3) & 1) * 16) << 4);
            cp16(st + aoff, Ag + (size_t)(mbase + r) * DIM + koff + c * 8);
            cp16(st + GS_MAT + boff, Bg + (size_t)(nbase + r) * DIM + koff + c * 8);
        }
    };

    #pragma unroll
    for (int i = 0; i < 2; i++)
        #pragma unroll
        for (int j = 0; j < 8; j++)
            #pragma unroll
            for (int t = 0; t < 4; t++) acc.a[i][j][t] = 0.f;

    load_stage(0, 0); CP_COMMIT();
    load_stage(1, 1); CP_COMMIT();

    for (int kt = 0; kt < GS_NKT; ++kt) {
        CP_WAIT(1);          // stage kt complete
        __syncthreads();     // visible; compute(kt-1) done
        if (kt + 2 < GS_NKT) load_stage(kt + 2, (kt + 2) % 3);
        CP_COMMIT();         // always commit (empty ok)
        const uint32_t stg = sb + (kt % 3) * GS_STAGE;
        #pragma unroll
        for (int s = 0; s < 4; ++s) {   // four k16 slabs per k-tile
            const uint32_t aA = stg + (s << 12) + ((wm * 2) << 9) + lane * 16;
            const uint32_t bA = stg + GS_MAT + (s << 12) + ((wn * 4) << 9) + lane * 16;
            uint32_t a0[4], a1[4], b[4][4];
            LDSM_X4(a0, aA);
            LDSM_X4(a1, aA + 512);
            #pragma unroll
            for (int jt = 0; jt < 4; ++jt) LDSM_X4(b[jt], bA + jt * 512);
            #pragma unroll
            for (int jt = 0; jt < 4; ++jt) {
                MMA16816H(acc.a[0][2 * jt],     a0, b[jt][0], b[jt][1]);
                MMA16816H(acc.a[0][2 * jt + 1], a0, b[jt][2], b[jt][3]);
                MMA16816H(acc.a[1][2 * jt],     a1, b[jt][0], b[jt][1]);
                MMA16816H(acc.a[1][2 * jt + 1], a1, b[jt][2], b[jt][3]);
            }
        }
    }
    __syncthreads();
}

// merged QKV projection: blockIdx.z selects weight + epilogue flavor.
// z=0: q (rinv, headnorm, *qks*DIM*sqrt(HD)*log2e)  z=1: k (rinv, headnorm)
// z=2: v (rinv)
__global__ void __launch_bounds__(256) gemm_qkv(const float* __restrict__ qks) {
    extern __shared__ char smem[];
    const uint32_t sb = smem_u32(smem);
    const int tid = threadIdx.x;
    const int wid = tid >> 5, lane = tid & 31;
    const int wm = wid & 3, wn = wid >> 2;
    const int mbase = blockIdx.y * 128, nbase = blockIdx.x * 128;
    const int sel = blockIdx.z;

    GAcc acc;
    gemm_mainloop(g_x16, g_w16[sel], sb, tid, mbase, nbase, acc);

    const int lr0 = wm * 32 + (lane >> 2);
    // weight row-norm reciprocal
    {
        const float* rinv = g_rinv[sel];
        #pragma unroll
        for (int j = 0; j < 8; ++j) {
            const int col = nbase + wn * 64 + j * 8 + (lane & 3) * 2;
            const float s0 = rinv[col], s1 = rinv[col + 1];
            #pragma unroll
            for (int i = 0; i < 2; ++i) {
                acc.a[i][j][0] *= s0; acc.a[i][j][1] *= s1;
                acc.a[i][j][2] *= s0; acc.a[i][j][3] *= s1;
            }
        }
    }
    if (sel < 2) {
        // per-row l2 norm over this CTA's 128 cols (= one head)
        float ssq[4] = {0.f, 0.f, 0.f, 0.f};
        #pragma unroll
        for (int i = 0; i < 2; ++i)
            #pragma unroll
            for (int j = 0; j < 8; ++j) {
                ssq[2 * i]     += acc.a[i][j][0] * acc.a[i][j][0] + acc.a[i][j][1] * acc.a[i][j][1];
                ssq[2 * i + 1] += acc.a[i][j][2] * acc.a[i][j][2] + acc.a[i][j][3] * acc.a[i][j][3];
            }
        #pragma unroll
        for (int r = 0; r < 4; ++r) {
            ssq[r] += __shfl_xor_sync(0xffffffffu, ssq[r], 1);
            ssq[r] += __shfl_xor_sync(0xffffffffu, ssq[r], 2);
        }
        float* red = (float*)smem;   // reuse pipeline smem: [2][128]
        if ((lane & 3) == 0) {
            #pragma unroll
            for (int r = 0; r < 4; ++r)
                red[wn * 128 + lr0 + (r & 1) * 8 + (r >> 1) * 16] = ssq[r];
        }
        __syncthreads();
        float rn_[4];
        #pragma unroll
        for (int r = 0; r < 4; ++r) {
            const int lr = lr0 + (r & 1) * 8 + (r >> 1) * 16;
            rn_[r] = 1.f / fmaxf(sqrtf(red[lr] + red[128 + lr]), 1e-12f);
        }
        #pragma unroll
        for (int i = 0; i < 2; ++i)
            #pragma unroll
            for (int j = 0; j < 8; ++j) {
                acc.a[i][j][0] *= rn_[2 * i];     acc.a[i][j][1] *= rn_[2 * i];
                acc.a[i][j][2] *= rn_[2 * i + 1]; acc.a[i][j][3] *= rn_[2 * i + 1];
            }
    }
    __half* Ch = sel == 0 ? g_q16 : (sel == 1 ? g_k16 : g_v16);
    #pragma unroll
    for (int j = 0; j < 8; ++j) {
        const int col = nbase + wn * 64 + j * 8 + (lane & 3) * 2;
        float qm0 = 1.f, qm1 = 1.f;
        if (sel == 0) {
            // DIM * sqrt(HD) * log2(e)  (softmax uses ex2)
            const float C = 23170.475005920826f * 1.4426950408889634f;
            qm0 = qks[col] * C;
            qm1 = qks[col + 1] * C;
        }
        #pragma unroll
        for (int i = 0; i < 2; ++i) {
            const int row = mbase + lr0 + i * 16;
            *(uint32_t*)(Ch + (size_t)row * DI + col) =
                pack2h(acc.a[i][j][0] * qm0, acc.a[i][j][1] * qm1);
            *(uint32_t*)(Ch + (size_t)(row + 8) * DI + col) =
                pack2h(acc.a[i][j][2] * qm0, acc.a[i][j][3] * qm1);
        }
    }
}

// output projection: fp32 out, no scaling (Wout norm folded in attention)
__global__ void __launch_bounds__(256) gemm_out(float* __restrict__ C) {
    extern __shared__ char smem[];
    const uint32_t sb = smem_u32(smem);
    const int tid = threadIdx.x;
    const int wid = tid >> 5, lane = tid & 31;
    const int wm = wid & 3, wn = wid >> 2;
    const int mbase = blockIdx.y * 128, nbase = blockIdx.x * 128;

    GAcc acc;
    gemm_mainloop(g_o16, g_w16[3], sb, tid, mbase, nbase, acc);

    const int lr0 = wm * 32 + (lane >> 2);
    #pragma unroll
    for (int j = 0; j < 8; ++j) {
        const int col = nbase + wn * 64 + j * 8 + (lane & 3) * 2;
        #pragma unroll
        for (int i = 0; i < 2; ++i) {
            const int row = mbase + lr0 + i * 16;
            *(float2*)(C + (size_t)row * DIM + col) =
                make_float2(acc.a[i][j][0], acc.a[i][j][1]);
            *(float2*)(C + (size_t)(row + 8) * DIM + col) =
                make_float2(acc.a[i][j][2], acc.a[i][j][3]);
        }
    }
}

// ============ fp16 causal flash attention (exp2 domain), dbl-buffered K/V ===
// 64x64 tiles, 128 thr / 4 warps, warp = 16 Q rows. Tiles 64 rows x 256B.
#define AQ 0
#define AKV 16384      /* buffer b at AKV + b*32768: K 16KB then V 16KB */
#define A_SMEM 81920

__global__ void __launch_bounds__(128) attn16() {
    extern __shared__ char asm_[];
    const uint32_t sb = smem_u32(asm_);
    const int tid = threadIdx.x;
    const int wid = tid >> 5, lane = tid & 31;
    const int qt = 31 - blockIdx.x;          // longest work first
    const int bh = blockIdx.y;
    const int b = bh >> 4, h = bh & 15;
    const size_t base = (size_t)b * SEQ * DI + (size_t)h * HD;
    const __half *qp = g_q16 + base;
    const __half *kp = g_k16 + base, *vp = g_v16 + base;

    // Q + (K,V) tile 0 in one group
    #pragma unroll
    for (int it = 0; it < 8; ++it) {
        const int i = tid + it * 128;
        const int r = i >> 4, c = i & 15;
        const uint32_t s = (r << 8) + ((c ^ (r & 7)) << 4);
        cp16(sb + AQ + s, qp + (size_t)(qt * 64 + r) * DI + c * 8);
        const size_t g0 = (size_t)r * DI + c * 8;    // K/V tile 0 rows
        cp16(sb + AKV + s, kp + g0);
        cp16(sb + AKV + 16384 + s, vp + g0);
    }
    CP_COMMIT();

    float oAcc[16][4];
    #pragma unroll
    for (int i = 0; i < 16; i++)
        #pragma unroll
        for (int j = 0; j < 4; j++) oAcc[i][j] = 0.f;
    float m0 = -1e30f, m1 = -1e30f, l0 = 0.f, l1 = 0.f;

    for (int kt = 0; kt <= qt; ++kt) {
        CP_WAIT(0);
        __syncthreads();
        if (kt < qt) {   // prefetch next K/V into other buffer
            const uint32_t dst = sb + AKV + ((kt + 1) & 1) * 32768;
            #pragma unroll
            for (int it = 0; it < 8; ++it) {
                const int i = tid + it * 128;
                const int r = i >> 4, c = i & 15;
                const size_t g = (size_t)((kt + 1) * 64 + r) * DI + c * 8;
                const uint32_t s = (r << 8) + ((c ^ (r & 7)) << 4);
                cp16(dst + s, kp + g);
                cp16(dst + 16384 + s, vp + g);
            }
            CP_COMMIT();
        }
        const uint32_t KB = sb + AKV + (kt & 1) * 32768;
        const uint32_t VB = KB + 16384;

        // ---- S = Q K^T (already in log2 domain via q scaling) ----
        float sAcc[8][4];
        #pragma unroll
        for (int i = 0; i < 8; i++)
            #pragma unroll
            for (int j = 0; j < 4; j++) sAcc[i][j] = 0.f;

        #pragma unroll
        for (int kk = 0; kk < 8; ++kk) {
            const int arow = wid * 16 + (lane & 15);
            const int achk = 2 * kk + (lane >> 4);
            const uint32_t aoff = (arow << 8) + ((achk ^ (arow & 7)) << 4);
            uint32_t qf[4];
            LDSM_X4(qf, sb + AQ + aoff);
            const int brow_ = (lane & 7) + ((lane >> 4) & 1) * 8;
            const int bchk = 2 * kk + ((lane >> 3) & 1);
            #pragma unroll
            for (int g = 0; g < 4; ++g) {
                const int brow = g * 16 + brow_;
                const uint32_t boff = (brow << 8) + ((bchk ^ (brow & 7)) << 4);
                uint32_t kf[4];
                LDSM_X4(kf, KB + boff);
                MMA16816H(sAcc[2 * g],     qf, kf[0], kf[1]);
                MMA16816H(sAcc[2 * g + 1], qf, kf[2], kf[3]);
            }
        }

        if (kt == qt) {   // causal mask on diagonal tile
            const int colb = (lane & 3) * 2;
            const int rowa = wid * 16 + (lane >> 2);
            #pragma unroll
            for (int jt = 0; jt < 8; ++jt) {
                const int c0 = jt * 8 + colb;
                if (c0 > rowa)     sAcc[jt][0] = -1e30f;
                if (c0 + 1 > rowa) sAcc[jt][1] = -1e30f;
                if (c0 > rowa + 8)     sAcc[jt][2] = -1e30f;
                if (c0 + 1 > rowa + 8) sAcc[jt][3] = -1e30f;
            }
        }

        // ---- online softmax in exp2 domain ----
        float mx0 = -1e30f, mx1 = -1e30f;
        #pragma unroll
        for (int jt = 0; jt < 8; ++jt) {
            mx0 = fmaxf(mx0, fmaxf(sAcc[jt][0], sAcc[jt][1]));
            mx1 = fmaxf(mx1, fmaxf(sAcc[jt][2], sAcc[jt][3]));
        }
        mx0 = fmaxf(mx0, __shfl_xor_sync(0xffffffffu, mx0, 1));
        mx0 = fmaxf(mx0, __shfl_xor_sync(0xffffffffu, mx0, 2));
        mx1 = fmaxf(mx1, __shfl_xor_sync(0xffffffffu, mx1, 1));
        mx1 = fmaxf(mx1, __shfl_xor_sync(0xffffffffu, mx1, 2));
        const float mn0 = fmaxf(m0, mx0), mn1 = fmaxf(m1, mx1);
        const float scl0 = ex2f(m0 - mn0), scl1 = ex2f(m1 - mn1);
        m0 = mn0; m1 = mn1;

        uint32_t ph[8][2];
        float rs0 = 0.f, rs1 = 0.f;
        #pragma unroll
        for (int jt = 0; jt < 8; ++jt) {
            const float p0 = ex2f(sAcc[jt][0] - mn0);
            const float p1 = ex2f(sAcc[jt][1] - mn0);
            const float p2 = ex2f(sAcc[jt][2] - mn1);
            const float p3 = ex2f(sAcc[jt][3] - mn1);
            rs0 += p0 + p1;
            rs1 += p2 + p3;
            ph[jt][0] = pack2h(p0, p1);
            ph[jt][1] = pack2h(p2, p3);
        }
        rs0 += __shfl_xor_sync(0xffffffffu, rs0, 1);
        rs0 += __shfl_xor_sync(0xffffffffu, rs0, 2);
        rs1 += __shfl_xor_sync(0xffffffffu, rs1, 1);
        rs1 += __shfl_xor_sync(0xffffffffu, rs1, 2);
        l0 = l0 * scl0 + rs0;
        l1 = l1 * scl1 + rs1;
        #pragma unroll
        for (int dt = 0; dt < 16; ++dt) {
            oAcc[dt][0] *= scl0; oAcc[dt][1] *= scl0;
            oAcc[dt][2] *= scl1; oAcc[dt][3] *= scl1;
        }

        // ---- O += P V (V via ldmatrix.trans) ----
        #pragma unroll
        for (int t = 0; t < 4; ++t) {
            uint32_t pa[4] = {ph[2 * t][0], ph[2 * t][1], ph[2 * t + 1][0], ph[2 * t + 1][1]};
            const int vrow = t * 16 + (lane & 7) + ((lane >> 3) & 1) * 8;
            #pragma unroll
            for (int g = 0; g < 8; ++g) {
                const int vchk = 2 * g + (lane >> 4);
                const uint32_t voff = (vrow << 8) + ((vchk ^ (vrow & 7)) << 4);
                uint32_t vf[4];
                LDSM_X4_T(vf, VB + voff);
                MMA16816H(oAcc[2 * g],     pa, vf[0], vf[1]);
                MMA16816H(oAcc[2 * g + 1], pa, vf[2], vf[3]);
            }
        }
    }

    // ---- epilogue: /l, fold Wout col-norm, emit fp16 ----
    const float li0 = 1.f / l0, li1 = 1.f / l1;
    const int row0 = qt * 64 + wid * 16 + (lane >> 2);
    const int colb = (lane & 3) * 2;
    __half* op = g_o16 + base;
    #pragma unroll
    for (int dt = 0; dt < 16; ++dt) {
        const int d = dt * 8 + colb;
        const float2 ro = *(const float2*)&g_rinv[3][h * HD + d];
        *(uint32_t*)(op + (size_t)row0 * DI + d) =
            pack2h(oAcc[dt][0] * li0 * ro.x, oAcc[dt][1] * li0 * ro.y);
        *(uint32_t*)(op + (size_t)(row0 + 8) * DI + d) =
            pack2h(oAcc[dt][2] * li1 * ro.x, oAcc[dt][3] * li1 * ro.y);
    }
}

// ============================== host side ====================================
extern "C" void kernel_launch(void* const* d_in, const int* in_sizes, int n_in,
                              void* d_out, int out_size) {
    (void)in_sizes; (void)n_in; (void)out_size;
    const float* x    = (const float*)d_in[0];
    const float* Wq   = (const float*)d_in[1];
    const float* Wk   = (const float*)d_in[2];
    const float* Wv   = (const float*)d_in[3];
    const float* Wout = (const float*)d_in[4];
    const float* qk   = (const float*)d_in[5];
    float* out = (float*)d_out;

    __half *px, *pw;
    cudaGetSymbolAddress((void**)&px, g_x16);
    cudaGetSymbolAddress((void**)&pw, g_w16);

    const size_t WSZ = (size_t)DIM * DIM;
    const int gsmem = 3 * GS_STAGE;   // 96KB
    cudaFuncSetAttribute(gemm_qkv, cudaFuncAttributeMaxDynamicSharedMemorySize, gsmem);
    cudaFuncSetAttribute(gemm_out, cudaFuncAttributeMaxDynamicSharedMemorySize, gsmem);
    cudaFuncSetAttribute(attn16, cudaFuncAttributeMaxDynamicSharedMemorySize, A_SMEM);

    // 0-2: converts (+ fused qkv row norms)
    convert_flat16<<<(MTOT * DIM / 4) / 256, 256>>>((const float4*)x, (uint32_t*)px);
    convert_wqkv16<<<dim3(DIM, 3), 256>>>(Wq, Wk, Wv, pw);
    convert_flat16<<<(DIM * DIM / 4) / 256, 256>>>(
        (const float4*)Wout, (uint32_t*)(pw + 3 * WSZ));

    // 3: merged QKV projection (launch idx 3 == ncu capture slot)
    gemm_qkv<<<dim3(DI / 128, MTOT / 128, 3), 256, gsmem>>>(qk);

    // 4-5: Wout column norm (needed only by attention epilogue)
    colnorm_part<<<dim3(DIM / 256, 16), 256>>>(Wout);
    colnorm_fin<<<DIM / 256, 256>>>();

    // 6: attention (emits o fp16, Wout col-norm folded)
    attn16<<<dim3(SEQ / 64, BATCH * HEADS), 128, A_SMEM>>>();

    // 7: output projection
    gemm_out<<<dim3(DIM / 128, MTOT / 128), 256, gsmem>>>(out);
}

// round 9
// speedup vs baseline: 6.2974x; 1.0053x over previous
#include <cuda_runtime.h>
#include <cuda_fp16.h>
#include <math.h>
#include <stdint.h>

#define BATCH 2
#define SEQ 2048
#define DIM 2048
#define HEADS 16
#define HD 128
#define DI 2048           /* HEADS*HD */
#define MTOT (BATCH*SEQ)  /* 4096 */

// ---------------- scratch (device globals: allocation-free rule) ------------
__device__ float g_rinv[4][DIM];     // 0:Wq rows 1:Wk rows 2:Wv rows 3:Wout cols
__device__ float g_colpart[16][DIM];
__device__ __half g_x16[(size_t)MTOT * DIM];
__device__ __half g_w16[4][(size_t)DIM * DIM];   // q,k,v,out
__device__ __half g_q16[(size_t)MTOT * DI];
__device__ __half g_k16[(size_t)MTOT * DI];
__device__ __half g_v16[(size_t)MTOT * DI];
__device__ __half g_o16[(size_t)MTOT * DI];

// ============================ PTX helpers (sm_80+ portable) =================
__device__ __forceinline__ uint32_t smem_u32(const void* p) {
    uint32_t a;
    asm("{ .reg .u64 t; cvta.to.shared.u64 t, %1; cvt.u32.u64 %0, t; }"
        : "=r"(a) : "l"(p));
    return a;
}

__device__ __forceinline__ void cp16(uint32_t saddr, const void* g) {
    asm volatile("cp.async.cg.shared.global [%0], [%1], 16;"
                 :: "r"(saddr), "l"(g) : "memory");
}
#define CP_COMMIT() asm volatile("cp.async.commit_group;" ::: "memory")
#define CP_WAIT(n)  asm volatile("cp.async.wait_group %0;" :: "n"(n) : "memory")

#define LDSM_X4(r, addr) \
    asm volatile("ldmatrix.sync.aligned.m8n8.x4.shared.b16 {%0,%1,%2,%3}, [%4];" \
        : "=r"((r)[0]), "=r"((r)[1]), "=r"((r)[2]), "=r"((r)[3]) : "r"(addr))

#define LDSM_X4_T(r, addr) \
    asm volatile("ldmatrix.sync.aligned.m8n8.x4.trans.shared.b16 {%0,%1,%2,%3}, [%4];" \
        : "=r"((r)[0]), "=r"((r)[1]), "=r"((r)[2]), "=r"((r)[3]) : "r"(addr))

#define MMA16816H(d, a, b0, b1) \
    asm volatile("mma.sync.aligned.m16n8k16.row.col.f32.f16.f16.f32 " \
        "{%0,%1,%2,%3}, {%4,%5,%6,%7}, {%8,%9}, {%0,%1,%2,%3};" \
        : "+f"((d)[0]), "+f"((d)[1]), "+f"((d)[2]), "+f"((d)[3]) \
        : "r"((a)[0]), "r"((a)[1]), "r"((a)[2]), "r"((a)[3]), "r"(b0), "r"(b1))

__device__ __forceinline__ uint32_t pack2h(float a, float b) {
    uint32_t r;
    asm("cvt.rn.f16x2.f32 %0, %1, %2;" : "=r"(r) : "f"(b), "f"(a));
    return r;
}
__device__ __forceinline__ float ex2f(float x) {
    float r;
    asm("ex2.approx.ftz.f32 %0, %1;" : "=f"(r) : "f"(x));
    return r;
}

// ================= fp32 -> fp16 converters (+ fused norms) ==================
__global__ void convert_flat16(const float4* __restrict__ W, uint32_t* __restrict__ o) {
    int i = blockIdx.x * 256 + threadIdx.x;
    float4 v = W[i];
    o[2 * i] = pack2h(v.x, v.y);
    o[2 * i + 1] = pack2h(v.z, v.w);
}

// fused q/k/v weight convert: one block per (row, which); + row l2 norm recip
__global__ void convert_wqkv16(const float* __restrict__ Wq,
                               const float* __restrict__ Wk,
                               const float* __restrict__ Wv,
                               __half* __restrict__ o) {
    __shared__ float red[8];
    const int row = blockIdx.x, sel = blockIdx.y, tid = threadIdx.x;
    const float* W = sel == 0 ? Wq : (sel == 1 ? Wk : Wv);
    const float4* p = (const float4*)(W + (size_t)row * DIM);
    uint32_t* op = (uint32_t*)(o + (size_t)sel * DIM * DIM + (size_t)row * DIM);
    float s = 0.f;
    #pragma unroll
    for (int i = tid; i < DIM / 4; i += 256) {
        float4 v = p[i];
        s += v.x * v.x + v.y * v.y + v.z * v.z + v.w * v.w;
        op[2 * i] = pack2h(v.x, v.y);
        op[2 * i + 1] = pack2h(v.z, v.w);
    }
    #pragma unroll
    for (int off = 16; off; off >>= 1) s += __shfl_xor_sync(0xffffffffu, s, off);
    if ((tid & 31) == 0) red[tid >> 5] = s;
    __syncthreads();
    if (tid == 0) {
        float t = 0.f;
        #pragma unroll
        for (int i = 0; i < 8; i++) t += red[i];
        g_rinv[sel][row] = 1.f / fmaxf(sqrtf(t), 1e-12f);
    }
}

// Wout column-norm: two-phase deterministic parallel reduce
__global__ void colnorm_part(const float* __restrict__ W) {
    const int col = blockIdx.x * 256 + threadIdx.x;
    const int r0 = blockIdx.y * 128;
    float s = 0.f;
    for (int r = 0; r < 128; ++r) {
        float v = W[(size_t)(r0 + r) * DI + col];
        s += v * v;
    }
    g_colpart[blockIdx.y][col] = s;
}
__global__ void colnorm_fin() {
    int c = blockIdx.x * 256 + threadIdx.x;
    float s = 0.f;
    #pragma unroll
    for (int i = 0; i < 16; ++i) s += g_colpart[i][c];
    g_rinv[3][c] = 1.f / fmaxf(sqrtf(s), 1e-12f);
}

// =================== fp16 single-pass NT GEMM, 256x128x64 tiles ==============
// 512 thr / 16 warps (wm 0..7 x wn 0..1), warp tile 32x64, 4-stage cp.async,
// 1 CTA/SM, one sync per k-tile. Stage = A 32KB + B 16KB = 48KB.
#define GA_MAT 32768
#define GS_STAGE 49152
#define GS_NKT (DIM / 64)   /* 32 */

struct GAcc { float a[2][8][4]; };

__device__ __forceinline__ void gemm_mainloop(
    const __half* __restrict__ Ag, const __half* __restrict__ Bg,
    uint32_t sb, int tid, int mbase, int nbase, GAcc& acc)
{
    const int wid = tid >> 5, lane = tid & 31;
    const int wm = wid >> 1, wn = wid & 1;

    auto load_stage = [&](int kt, int buf) {
        const uint32_t st = sb + buf * GS_STAGE;
        const int koff = kt * 64;
        // A: 256 rows x 64k fp16 = 32KB; layout [slab(c>>1) 8KB][rowgrp 512B][kchunk 256B][row 16B]
        #pragma unroll
        for (int h = 0; h < 4; ++h) {
            const int cid = tid + h * 512;
            const int r = cid >> 3, c = cid & 7;
            const uint32_t aoff = ((c >> 1) << 13) + ((r >> 4) << 9) +
                (((r & 15) + (c & 1) * 16) << 4);
            cp16(st + aoff, Ag + (size_t)(mbase + r) * DIM + koff + c * 8);
        }
        // B: 128 rows x 64k fp16 = 16KB
        #pragma unroll
        for (int h = 0; h < 2; ++h) {
            const int cid = tid + h * 512;
            const int r = cid >> 3, c = cid & 7;
            const uint32_t boff = ((c >> 1) << 12) + ((r >> 4) << 9) +
                (((r & 7) + (c & 1) * 8 + ((r >> 3) & 1) * 16) << 4);
            cp16(st + GA_MAT + boff, Bg + (size_t)(nbase + r) * DIM + koff + c * 8);
        }
    };

    #pragma unroll
    for (int i = 0; i < 2; i++)
        #pragma unroll
        for (int j = 0; j < 8; j++)
            #pragma unroll
            for (int t = 0; t < 4; t++) acc.a[i][j][t] = 0.f;

    load_stage(0, 0); CP_COMMIT();
    load_stage(1, 1); CP_COMMIT();
    load_stage(2, 2); CP_COMMIT();

    for (int kt = 0; kt < GS_NKT; ++kt) {
        CP_WAIT(2);          // stage kt complete (kt+1, kt+2 may be pending)
        __syncthreads();     // visible; compute(kt-1) done
        if (kt + 3 < GS_NKT) load_stage(kt + 3, (kt + 3) & 3);
        CP_COMMIT();         // always commit (empty ok) to keep wait semantics
        const uint32_t stg = sb + (kt & 3) * GS_STAGE;
        #pragma unroll
        for (int s = 0; s < 4; ++s) {   // four k16 slabs per k-tile
            const uint32_t aA = stg + (s << 13) + ((wm * 2) << 9) + lane * 16;
            const uint32_t bA = stg + GA_MAT + (s << 12) + ((wn * 4) << 9) + lane * 16;
            uint32_t a0[4], a1[4], b[4][4];
            LDSM_X4(a0, aA);
            LDSM_X4(a1, aA + 512);
            #pragma unroll
            for (int jt = 0; jt < 4; ++jt) LDSM_X4(b[jt], bA + jt * 512);
            #pragma unroll
            for (int jt = 0; jt < 4; ++jt) {
                MMA16816H(acc.a[0][2 * jt],     a0, b[jt][0], b[jt][1]);
                MMA16816H(acc.a[0][2 * jt + 1], a0, b[jt][2], b[jt][3]);
                MMA16816H(acc.a[1][2 * jt],     a1, b[jt][0], b[jt][1]);
                MMA16816H(acc.a[1][2 * jt + 1], a1, b[jt][2], b[jt][3]);
            }
        }
    }
    __syncthreads();
}

// merged QKV projection: blockIdx.z selects weight + epilogue flavor.
// z=0: q (rinv, headnorm, *qks*DIM*sqrt(HD)*log2e)  z=1: k (rinv, headnorm)
// z=2: v (rinv)
__global__ void __launch_bounds__(512, 1) gemm_qkv(const float* __restrict__ qks) {
    extern __shared__ char smem[];
    const uint32_t sb = smem_u32(smem);
    const int tid = threadIdx.x;
    const int wid = tid >> 5, lane = tid & 31;
    const int wm = wid >> 1, wn = wid & 1;
    const int mbase = blockIdx.y * 256, nbase = blockIdx.x * 128;
    const int sel = blockIdx.z;

    GAcc acc;
    gemm_mainloop(g_x16, g_w16[sel], sb, tid, mbase, nbase, acc);

    const int lr0 = wm * 32 + (lane >> 2);
    // weight row-norm reciprocal
    {
        const float* rinv = g_rinv[sel];
        #pragma unroll
        for (int j = 0; j < 8; ++j) {
            const int col = nbase + wn * 64 + j * 8 + (lane & 3) * 2;
            const float s0 = rinv[col], s1 = rinv[col + 1];
            #pragma unroll
            for (int i = 0; i < 2; ++i) {
                acc.a[i][j][0] *= s0; acc.a[i][j][1] *= s1;
                acc.a[i][j][2] *= s0; acc.a[i][j][3] *= s1;
            }
        }
    }
    if (sel < 2) {
        // per-row l2 norm over this CTA's 128 cols (= one head)
        float ssq[4] = {0.f, 0.f, 0.f, 0.f};
        #pragma unroll
        for (int i = 0; i < 2; ++i)
            #pragma unroll
            for (int j = 0; j < 8; ++j) {
                ssq[2 * i]     += acc.a[i][j][0] * acc.a[i][j][0] + acc.a[i][j][1] * acc.a[i][j][1];
                ssq[2 * i + 1] += acc.a[i][j][2] * acc.a[i][j][2] + acc.a[i][j][3] * acc.a[i][j][3];
            }
        #pragma unroll
        for (int r = 0; r < 4; ++r) {
            ssq[r] += __shfl_xor_sync(0xffffffffu, ssq[r], 1);
            ssq[r] += __shfl_xor_sync(0xffffffffu, ssq[r], 2);
        }
        float* red = (float*)smem;   // reuse pipeline smem: [2][256]
        if ((lane & 3) == 0) {
            #pragma unroll
            for (int r = 0; r < 4; ++r)
                red[wn * 256 + lr0 + (r & 1) * 8 + (r >> 1) * 16] = ssq[r];
        }
        __syncthreads();
        float rn_[4];
        #pragma unroll
        for (int r = 0; r < 4; ++r) {
            const int lr = lr0 + (r & 1) * 8 + (r >> 1) * 16;
            rn_[r] = 1.f / fmaxf(sqrtf(red[lr] + red[256 + lr]), 1e-12f);
        }
        #pragma unroll
        for (int i = 0; i < 2; ++i)
            #pragma unroll
            for (int j = 0; j < 8; ++j) {
                acc.a[i][j][0] *= rn_[2 * i];     acc.a[i][j][1] *= rn_[2 * i];
                acc.a[i][j][2] *= rn_[2 * i + 1]; acc.a[i][j][3] *= rn_[2 * i + 1];
            }
    }
    __half* Ch = sel == 0 ? g_q16 : (sel == 1 ? g_k16 : g_v16);
    #pragma unroll
    for (int j = 0; j < 8; ++j) {
        const int col = nbase + wn * 64 + j * 8 + (lane & 3) * 2;
        float qm0 = 1.f, qm1 = 1.f;
        if (sel == 0) {
            // DIM * sqrt(HD) * log2(e)  (softmax uses ex2)
            const float C = 23170.475005920826f * 1.4426950408889634f;
            qm0 = qks[col] * C;
            qm1 = qks[col + 1] * C;
        }
        #pragma unroll
        for (int i = 0; i < 2; ++i) {
            const int row = mbase + lr0 + i * 16;
            *(uint32_t*)(Ch + (size_t)row * DI + col) =
                pack2h(acc.a[i][j][0] * qm0, acc.a[i][j][1] * qm1);
            *(uint32_t*)(Ch + (size_t)(row + 8) * DI + col) =
                pack2h(acc.a[i][j][2] * qm0, acc.a[i][j][3] * qm1);
        }
    }
}

// output projection: fp32 out, no scaling (Wout norm folded in attention)
__global__ void __launch_bounds__(512, 1) gemm_out(float* __restrict__ C) {
    extern __shared__ char smem[];
    const uint32_t sb = smem_u32(smem);
    const int tid = threadIdx.x;
    const int wid = tid >> 5, lane = tid & 31;
    const int wm = wid >> 1, wn = wid & 1;
    const int mbase = blockIdx.y * 256, nbase = blockIdx.x * 128;

    GAcc acc;
    gemm_mainloop(g_o16, g_w16[3], sb, tid, mbase, nbase, acc);

    const int lr0 = wm * 32 + (lane >> 2);
    #pragma unroll
    for (int j = 0; j < 8; ++j) {
        const int col = nbase + wn * 64 + j * 8 + (lane & 3) * 2;
        #pragma unroll
        for (int i = 0; i < 2; ++i) {
            const int row = mbase + lr0 + i * 16;
            *(float2*)(C + (size_t)row * DIM + col) =
                make_float2(acc.a[i][j][0], acc.a[i][j][1]);
            *(float2*)(C + (size_t)(row + 8) * DIM + col) =
                make_float2(acc.a[i][j][2], acc.a[i][j][3]);
        }
    }
}

// ============ fp16 causal flash attention (exp2 domain), dbl-buffered K/V ===
// 64x64 tiles, 128 thr / 4 warps, warp = 16 Q rows. Tiles 64 rows x 256B.
#define AQ 0
#define AKV 16384      /* buffer b at AKV + b*32768: K 16KB then V 16KB */
#define A_SMEM 81920

__global__ void __launch_bounds__(128) attn16() {
    extern __shared__ char asm_[];
    const uint32_t sb = smem_u32(asm_);
    const int tid = threadIdx.x;
    const int wid = tid >> 5, lane = tid & 31;
    const int qt = 31 - blockIdx.x;          // longest work first
    const int bh = blockIdx.y;
    const int b = bh >> 4, h = bh & 15;
    const size_t base = (size_t)b * SEQ * DI + (size_t)h * HD;
    const __half *qp = g_q16 + base;
    const __half *kp = g_k16 + base, *vp = g_v16 + base;

    // Q + (K,V) tile 0 in one group
    #pragma unroll
    for (int it = 0; it < 8; ++it) {
        const int i = tid + it * 128;
        const int r = i >> 4, c = i & 15;
        const uint32_t s = (r << 8) + ((c ^ (r & 7)) << 4);
        cp16(sb + AQ + s, qp + (size_t)(qt * 64 + r) * DI + c * 8);
        const size_t g0 = (size_t)r * DI + c * 8;    // K/V tile 0 rows
        cp16(sb + AKV + s, kp + g0);
        cp16(sb + AKV + 16384 + s, vp + g0);
    }
    CP_COMMIT();

    float oAcc[16][4];
    #pragma unroll
    for (int i = 0; i < 16; i++)
        #pragma unroll
        for (int j = 0; j < 4; j++) oAcc[i][j] = 0.f;
    float m0 = -1e30f, m1 = -1e30f, l0 = 0.f, l1 = 0.f;

    for (int kt = 0; kt <= qt; ++kt) {
        CP_WAIT(0);
        __syncthreads();
        if (kt < qt) {   // prefetch next K/V into other buffer
            const uint32_t dst = sb + AKV + ((kt + 1) & 1) * 32768;
            #pragma unroll
            for (int it = 0; it < 8; ++it) {
                const int i = tid + it * 128;
                const int r = i >> 4, c = i & 15;
                const size_t g = (size_t)((kt + 1) * 64 + r) * DI + c * 8;
                const uint32_t s = (r << 8) + ((c ^ (r & 7)) << 4);
                cp16(dst + s, kp + g);
                cp16(dst + 16384 + s, vp + g);
            }
            CP_COMMIT();
        }
        const uint32_t KB = sb + AKV + (kt & 1) * 32768;
        const uint32_t VB = KB + 16384;

        // ---- S = Q K^T (already in log2 domain via q scaling) ----
        float sAcc[8][4];
        #pragma unroll
        for (int i = 0; i < 8; i++)
            #pragma unroll
            for (int j = 0; j < 4; j++) sAcc[i][j] = 0.f;

        #pragma unroll
        for (int kk = 0; kk < 8; ++kk) {
            const int arow = wid * 16 + (lane & 15);
            const int achk = 2 * kk + (lane >> 4);
            const uint32_t aoff = (arow << 8) + ((achk ^ (arow & 7)) << 4);
            uint32_t qf[4];
            LDSM_X4(qf, sb + AQ + aoff);
            const int brow_ = (lane & 7) + ((lane >> 4) & 1) * 8;
            const int bchk = 2 * kk + ((lane >> 3) & 1);
            #pragma unroll
            for (int g = 0; g < 4; ++g) {
                const int brow = g * 16 + brow_;
                const uint32_t boff = (brow << 8) + ((bchk ^ (brow & 7)) << 4);
                uint32_t kf[4];
                LDSM_X4(kf, KB + boff);
                MMA16816H(sAcc[2 * g],     qf, kf[0], kf[1]);
                MMA16816H(sAcc[2 * g + 1], qf, kf[2], kf[3]);
            }
        }

        if (kt == qt) {   // causal mask on diagonal tile
            const int colb = (lane & 3) * 2;
            const int rowa = wid * 16 + (lane >> 2);
            #pragma unroll
            for (int jt = 0; jt < 8; ++jt) {
                const int c0 = jt * 8 + colb;
                if (c0 > rowa)     sAcc[jt][0] = -1e30f;
                if (c0 + 1 > rowa) sAcc[jt][1] = -1e30f;
                if (c0 > rowa + 8)     sAcc[jt][2] = -1e30f;
                if (c0 + 1 > rowa + 8) sAcc[jt][3] = -1e30f;
            }
        }

        // ---- online softmax in exp2 domain ----
        float mx0 = -1e30f, mx1 = -1e30f;
        #pragma unroll
        for (int jt = 0; jt < 8; ++jt) {
            mx0 = fmaxf(mx0, fmaxf(sAcc[jt][0], sAcc[jt][1]));
            mx1 = fmaxf(mx1, fmaxf(sAcc[jt][2], sAcc[jt][3]));
        }
        mx0 = fmaxf(mx0, __shfl_xor_sync(0xffffffffu, mx0, 1));
        mx0 = fmaxf(mx0, __shfl_xor_sync(0xffffffffu, mx0, 2));
        mx1 = fmaxf(mx1, __shfl_xor_sync(0xffffffffu, mx1, 1));
        mx1 = fmaxf(mx1, __shfl_xor_sync(0xffffffffu, mx1, 2));
        const float mn0 = fmaxf(m0, mx0), mn1 = fmaxf(m1, mx1);
        const float scl0 = ex2f(m0 - mn0), scl1 = ex2f(m1 - mn1);
        m0 = mn0; m1 = mn1;

        uint32_t ph[8][2];
        float rs0 = 0.f, rs1 = 0.f;
        #pragma unroll
        for (int jt = 0; jt < 8; ++jt) {
            const float p0 = ex2f(sAcc[jt][0] - mn0);
            const float p1 = ex2f(sAcc[jt][1] - mn0);
            const float p2 = ex2f(sAcc[jt][2] - mn1);
            const float p3 = ex2f(sAcc[jt][3] - mn1);
            rs0 += p0 + p1;
            rs1 += p2 + p3;
            ph[jt][0] = pack2h(p0, p1);
            ph[jt][1] = pack2h(p2, p3);
        }
        rs0 += __shfl_xor_sync(0xffffffffu, rs0, 1);
        rs0 += __shfl_xor_sync(0xffffffffu, rs0, 2);
        rs1 += __shfl_xor_sync(0xffffffffu, rs1, 1);
        rs1 += __shfl_xor_sync(0xffffffffu, rs1, 2);
        l0 = l0 * scl0 + rs0;
        l1 = l1 * scl1 + rs1;
        #pragma unroll
        for (int dt = 0; dt < 16; ++dt) {
            oAcc[dt][0] *= scl0; oAcc[dt][1] *= scl0;
            oAcc[dt][2] *= scl1; oAcc[dt][3] *= scl1;
        }

        // ---- O += P V (V via ldmatrix.trans) ----
        #pragma unroll
        for (int t = 0; t < 4; ++t) {
            uint32_t pa[4] = {ph[2 * t][0], ph[2 * t][1], ph[2 * t + 1][0], ph[2 * t + 1][1]};
            const int vrow = t * 16 + (lane & 7) + ((lane >> 3) & 1) * 8;
            #pragma unroll
            for (int g = 0; g < 8; ++g) {
                const int vchk = 2 * g + (lane >> 4);
                const uint32_t voff = (vrow << 8) + ((vchk ^ (vrow & 7)) << 4);
                uint32_t vf[4];
                LDSM_X4_T(vf, VB + voff);
                MMA16816H(oAcc[2 * g],     pa, vf[0], vf[1]);
                MMA16816H(oAcc[2 * g + 1], pa, vf[2], vf[3]);
            }
        }
    }

    // ---- epilogue: /l, fold Wout col-norm, emit fp16 ----
    const float li0 = 1.f / l0, li1 = 1.f / l1;
    const int row0 = qt * 64 + wid * 16 + (lane >> 2);
    const int colb = (lane & 3) * 2;
    __half* op = g_o16 + base;
    #pragma unroll
    for (int dt = 0; dt < 16; ++dt) {
        const int d = dt * 8 + colb;
        const float2 ro = *(const float2*)&g_rinv[3][h * HD + d];
        *(uint32_t*)(op + (size_t)row0 * DI + d) =
            pack2h(oAcc[dt][0] * li0 * ro.x, oAcc[dt][1] * li0 * ro.y);
        *(uint32_t*)(op + (size_t)(row0 + 8) * DI + d) =
            pack2h(oAcc[dt][2] * li1 * ro.x, oAcc[dt][3] * li1 * ro.y);
    }
}

// ============================== host side ====================================
extern "C" void kernel_launch(void* const* d_in, const int* in_sizes, int n_in,
                              void* d_out, int out_size) {
    (void)in_sizes; (void)n_in; (void)out_size;
    const float* x    = (const float*)d_in[0];
    const float* Wq   = (const float*)d_in[1];
    const float* Wk   = (const float*)d_in[2];
    const float* Wv   = (const float*)d_in[3];
    const float* Wout = (const float*)d_in[4];
    const float* qk   = (const float*)d_in[5];
    float* out = (float*)d_out;

    __half *px, *pw;
    cudaGetSymbolAddress((void**)&px, g_x16);
    cudaGetSymbolAddress((void**)&pw, g_w16);

    const size_t WSZ = (size_t)DIM * DIM;
    const int gsmem = 4 * GS_STAGE;   // 192KB
    cudaFuncSetAttribute(gemm_qkv, cudaFuncAttributeMaxDynamicSharedMemorySize, gsmem);
    cudaFuncSetAttribute(gemm_out, cudaFuncAttributeMaxDynamicSharedMemorySize, gsmem);
    cudaFuncSetAttribute(attn16, cudaFuncAttributeMaxDynamicSharedMemorySize, A_SMEM);

    // 0-2: converts (+ fused qkv row norms)
    convert_flat16<<<(MTOT * DIM / 4) / 256, 256>>>((const float4*)x, (uint32_t*)px);
    convert_wqkv16<<<dim3(DIM, 3), 256>>>(Wq, Wk, Wv, pw);
    convert_flat16<<<(DIM * DIM / 4) / 256, 256>>>(
        (const float4*)Wout, (uint32_t*)(pw + 3 * WSZ));

    // 3: merged QKV projection (launch idx 3 == ncu capture slot)
    gemm_qkv<<<dim3(DI / 128, MTOT / 256, 3), 512, gsmem>>>(qk);

    // 4-5: Wout column norm (needed only by attention epilogue)
    colnorm_part<<<dim3(DIM / 256, 16), 256>>>(Wout);
    colnorm_fin<<<DIM / 256, 256>>>();

    // 6: attention (emits o fp16, Wout col-norm folded)
    attn16<<<dim3(SEQ / 64, BATCH * HEADS), 128, A_SMEM>>>();

    // 7: output projection
    gemm_out<<<dim3(DIM / 128, MTOT / 256), 512, gsmem>>>(out);
}